// round 13
// baseline (speedup 1.0000x reference)
#include <cuda_runtime.h>
#include <cuda_fp16.h>
#include <cstdint>

// Decoder: 2-layer LSTM + Luong attention. T=B=S=64, H=E=1024, L=2.
// mma.sync fp16, 64x128 tiles (merged), 512 threads = 4 warpgroups with
// 4-way K-split, k16 chunks, 4-stage cp.async pipeline. Single-wave grids
// (144 blocks/step). Attention: fp32 scores, fp16-ctx weighted sum.

#define TT 64
#define BB 64
#define SS 64
#define HH 1024
#define BH (BB * HH)

typedef unsigned long long ull;
typedef __half h16;

__device__ __forceinline__ float sigm_(float x) { return 1.f / (1.f + expf(-x)); }
__device__ __forceinline__ void split2(float v, h16& hi, h16& lo) {
    hi = __float2half_rn(v);
    lo = __float2half_rn(v - __half2float(hi));
}

// ------------------------------- scratch -------------------------------
__device__ __align__(256) h16 g_Wih[8388608];      // [2][4096][1024]
__device__ __align__(256) h16 g_Whh[8388608];
__device__ __align__(256) h16 g_Win[1048576];
__device__ __align__(256) h16 g_Wo[2097152];       // [1024][2048]
__device__ __align__(256) h16 g_XEh[4194304], g_XEl[4194304];
__device__ __align__(256) h16 g_ctxH[4194304];     // fp16 copy of context
__device__ float g_X0[(size_t)4096 * 4096];        // [t*64+b][4096 gate cols]
__device__ float g_h0F[2][BH], g_h1F[4][BH], g_c0F[BH], g_c1F[BH];
__device__ __align__(256) h16 g_h0H[2][BH];
__device__ __align__(256) h16 g_h1H[4][BH];
__device__ __align__(256) h16 g_wcH[2][BH];
__device__ float g_qF[2][BH];
__device__ float g_attn[BB * SS];

// ----------------------------- ptx helpers -----------------------------
__device__ __forceinline__ uint32_t s2u(const void* p) {
    uint32_t a;
    asm("{ .reg .u64 t; cvta.to.shared.u64 t, %1; cvt.u32.u64 %0, t; }"
        : "=r"(a) : "l"(p));
    return a;
}
__device__ __forceinline__ void cpa16(uint32_t dst, const void* src) {
    asm volatile("cp.async.cg.shared.global [%0], [%1], 16;"
                 :: "r"(dst), "l"(src) : "memory");
}
__device__ __forceinline__ void ldsm4(uint32_t* r, uint32_t addr) {
    asm volatile("ldmatrix.sync.aligned.m8n8.x4.shared.b16 {%0,%1,%2,%3}, [%4];"
                 : "=r"(r[0]), "=r"(r[1]), "=r"(r[2]), "=r"(r[3]) : "r"(addr));
}
__device__ __forceinline__ void mma16816(float* d, const uint32_t* a, const uint32_t* b) {
    asm volatile(
        "mma.sync.aligned.m16n8k16.row.col.f32.f16.f16.f32 "
        "{%0,%1,%2,%3},{%4,%5,%6,%7},{%8,%9},{%0,%1,%2,%3};"
        : "+f"(d[0]), "+f"(d[1]), "+f"(d[2]), "+f"(d[3])
        : "r"(a[0]), "r"(a[1]), "r"(a[2]), "r"(a[3]), "r"(b[0]), "r"(b[1]));
}
__device__ __forceinline__ void barw(int wg) {
    asm volatile("bar.sync %0, 128;" :: "r"(wg + 1) : "memory");
}

// ---------------------------- GEMM segment -----------------------------
// C[64 m(batch), 128 n] = A @ W^T. 512 threads = 4 wgs of 128; each wg
// computes a K-slice into a partial accumulator; combined in epilogue.
// DUALA: A hi/lo pair sharing one W load (X0 precompute only).
// GATE: n cols = 4 gates x 32 hidden units. PAIR2: K=2048 (wg pair = half).
struct Seg {
    const h16 *A1, *A2;
    const h16 *W1, *W2;
    int wld, K;
    const float *addC, *bias1, *bias2;
    float *cSt, *hF;
    h16 *hH;
    float *outC; int ldC, doTanh;
};

// per-wg stage (k16), rows x 48B (32B data + 16B pad, conflict-free):
//   normal: A 64x48 = 3072 | W 128x48 = 6144            = 9216 B
//   DUALA : Ah 3072 | Al 3072 | W 6144                  = 12288 B
#define SMB_STEP (4 * 4 * 9216)
#define SMB_X0   (4 * 4 * 12288)

template <bool GATE, bool PAIR2, bool DUALA, int EPI>
__device__ void mgemm(const Seg& a, char* sm, int mblk, int nblk) {
    const int STG  = DUALA ? 12288 : 9216;
    const int WOFF = DUALA ? 6144 : 3072;
    const int tx = threadIdx.x;
    const int wg = tx >> 7;              // warpgroup 0..3
    const int wtx = tx & 127;
    const int warp = wtx >> 5, lane = tx & 31;
    const int wm = warp << 4;            // warp m offset; n covers all 128
    const uint32_t smb = s2u(sm) + wg * (4 * STG);

    // staging: thread -> (row 0..63, 16B unit 0..1); W also row+64
    const int sr = wtx >> 1, su = wtx & 1;
    const int am = mblk * 64 + sr;
    const int wrA = GATE ? ((sr >> 5) * HH + nblk * 32 + (sr & 31))
                         : (nblk * 128 + sr);
    const int r1 = sr + 64;
    const int wrB = GATE ? ((r1 >> 5) * HH + nblk * 32 + (r1 & 31))
                         : (nblk * 128 + r1);

    const h16 *a1, *a2, *w1;
    int kbase, Kwg;
    if (PAIR2) {
        int p = wg >> 1;
        a1 = p ? a.A2 : a.A1;
        w1 = p ? a.W2 : a.W1;
        a2 = nullptr;
        kbase = (wg & 1) << 9; Kwg = 512;
    } else {
        a1 = a.A1; a2 = a.A2; w1 = a.W1;
        Kwg = a.K >> 2; kbase = wg * Kwg;
    }
    const size_t arow = (size_t)am * 1024;
    const size_t wroA = (size_t)wrA * a.wld;
    const size_t wroB = (size_t)wrB * a.wld;

    float acc[16][4] = {};
    const int nc = Kwg >> 4;             // k16 chunks

    const uint32_t aoff = (uint32_t)((wm + (lane & 15)) * 48 + ((lane >> 4) << 4));
    const uint32_t boff = (uint32_t)(((((lane >> 4) << 3) + (lane & 7))) * 48
                                     + (((lane >> 3) & 1) << 4));

#define STAGE(c)                                                               \
    {                                                                          \
        int kl = kbase + ((c) << 4);                                           \
        uint32_t db = smb + ((c) & 3) * STG;                                   \
        uint32_t ro = sr * 48 + (su << 4);                                     \
        cpa16(db + ro, a1 + arow + kl + su * 8);                               \
        if (DUALA) cpa16(db + 3072 + ro, a2 + arow + kl + su * 8);             \
        cpa16(db + WOFF + ro, w1 + wroA + kl + su * 8);                        \
        cpa16(db + WOFF + ro + 64 * 48, w1 + wroB + kl + su * 8);              \
        asm volatile("cp.async.commit_group;" ::: "memory");                   \
    }

    STAGE(0) STAGE(1) STAGE(2)
    for (int c = 0; c < nc; ++c) {
        if (c + 3 < nc) {
            asm volatile("cp.async.wait_group 2;" ::: "memory");
            barw(wg);
            STAGE(c + 3)
        } else {
            asm volatile("cp.async.wait_group 0;" ::: "memory");
            barw(wg);
        }
        const uint32_t base = smb + (c & 3) * STG;
        uint32_t ah[4], al[4], bw[32];
        ldsm4(ah, base + aoff);
        if (DUALA) ldsm4(al, base + 3072 + aoff);
#pragma unroll
        for (int j = 0; j < 8; ++j)
            ldsm4(bw + 4 * j, base + WOFF + boff + j * 16 * 48);
#pragma unroll
        for (int nt = 0; nt < 16; ++nt) {
            mma16816(acc[nt], ah, bw + 2 * nt);
            if (DUALA) mma16816(acc[nt], al, bw + 2 * nt);
        }
    }
#undef STAGE
    __syncthreads();

    // stage partial C: wg i -> St[i*8448 ..], layout [col 0..127][row], pitch 66
    float* St = (float*)sm;
    float* Sw = St + wg * 8448;
    const int rr = wm + (lane >> 2);
#pragma unroll
    for (int nt = 0; nt < 16; ++nt) {
        int cc = nt * 8 + ((lane & 3) << 1);
        Sw[cc * 66 + rr]           = acc[nt][0];
        Sw[(cc + 1) * 66 + rr]     = acc[nt][1];
        Sw[cc * 66 + rr + 8]       = acc[nt][2];
        Sw[(cc + 1) * 66 + rr + 8] = acc[nt][3];
    }
    __syncthreads();

    if (EPI == 0) {      // fused LSTM cell: cols = gate*32 + jj
#pragma unroll
        for (int it = 0; it < 4; ++it) {
            int idx = tx + it * 512;
            int b = idx & 63, jj = idx >> 6;          // jj 0..31
            int jg = nblk * 32 + jj;
            float gi = St[jj * 66 + b]         + St[8448 + jj * 66 + b]
                     + St[16896 + jj * 66 + b] + St[25344 + jj * 66 + b];
            float gf = St[(32 + jj) * 66 + b]         + St[8448 + (32 + jj) * 66 + b]
                     + St[16896 + (32 + jj) * 66 + b] + St[25344 + (32 + jj) * 66 + b];
            float gg = St[(64 + jj) * 66 + b]         + St[8448 + (64 + jj) * 66 + b]
                     + St[16896 + (64 + jj) * 66 + b] + St[25344 + (64 + jj) * 66 + b];
            float go = St[(96 + jj) * 66 + b]         + St[8448 + (96 + jj) * 66 + b]
                     + St[16896 + (96 + jj) * 66 + b] + St[25344 + (96 + jj) * 66 + b];
            if (a.addC) {
                const float* ac = a.addC + (size_t)b * 4096 + jg;
                gi += ac[0]; gf += ac[1024]; gg += ac[2048]; go += ac[3072];
            }
            if (a.bias1) {
                gi += a.bias1[jg] + a.bias2[jg];
                gf += a.bias1[1024 + jg] + a.bias2[1024 + jg];
                gg += a.bias1[2048 + jg] + a.bias2[2048 + jg];
                go += a.bias1[3072 + jg] + a.bias2[3072 + jg];
            }
            float cc2 = sigm_(gf) * a.cSt[b * HH + jg] + sigm_(gi) * tanhf(gg);
            a.cSt[b * HH + jg] = cc2;
            float h = sigm_(go) * tanhf(cc2);
            a.hF[b * HH + jg] = h;
            a.hH[b * HH + jg] = __float2half_rn(h);
        }
    } else {             // plain store (optional bias / tanh)
#pragma unroll
        for (int it = 0; it < 16; ++it) {
            int idx = tx + it * 512;
            int row = idx >> 7, col = idx & 127;
            float v = St[col * 66 + row]         + St[8448 + col * 66 + row]
                    + St[16896 + col * 66 + row] + St[25344 + col * 66 + row];
            int cg = nblk * 128 + col;
            if (a.bias1) v += a.bias1[cg] + a.bias2[cg];
            if (a.doTanh) v = tanhf(v);
            a.outC[(size_t)(mblk * 64 + row) * a.ldC + cg] = v;
        }
    }
}

// ------------------------------ step kernel ----------------------------
// Single wave (144 blocks): order [ATTN, L1, L0, OUT, Q].
struct StepP {
    int nL1, nOut, nL0, nQ, nAt;
    Seg l1, o, l0, q;
    const float *atQ, *atCtx;
    const h16 *atCtxH;
    h16 *atWc;
    float* atP;
};

__global__ __launch_bounds__(512, 1) void step_k(StepP p) {
    extern __shared__ __align__(16) char sm[];
    const int bid = blockIdx.x;
    const int r0 = p.nAt, r1 = r0 + p.nL1, r2 = r1 + p.nL0, r3 = r2 + p.nOut;

    if (bid >= r0 && bid < r1) {
        mgemm<true, true, false, 0>(p.l1, sm, 0, bid - r0);
    } else if (bid >= r1 && bid < r2) {
        mgemm<true, false, false, 0>(p.l0, sm, 0, bid - r1);
    } else if (bid >= r2 && bid < r3) {
        mgemm<false, true, false, 1>(p.o, sm, 0, bid - r2);
    } else if (bid >= r3) {
        mgemm<false, false, false, 1>(p.q, sm, 0, bid - r3);
    } else {                              // ATTN: one block per batch b
        int b = bid;
        float* qs = (float*)sm;           // 1024 floats
        float* sc = qs + 1024;            // 64 floats
        const int tx = threadIdx.x;
        *(float2*)&qs[tx * 2] = *(const float2*)&p.atQ[(size_t)b * HH + tx * 2];
        __syncthreads();
        const int wid = tx >> 5, lane = tx & 31;
        for (int s = wid; s < SS; s += 16) {
            const float* cp = p.atCtx + ((size_t)s * BB + b) * HH;
            float acc = 0.f;
#pragma unroll
            for (int i = 0; i < 8; ++i) {
                float4 c4 = *(const float4*)(cp + i * 128 + lane * 4);
                float4 q4 = *(const float4*)&qs[i * 128 + lane * 4];
                acc += c4.x * q4.x + c4.y * q4.y + c4.z * q4.z + c4.w * q4.w;
            }
#pragma unroll
            for (int o = 16; o; o >>= 1) acc += __shfl_down_sync(0xFFFFFFFFu, acc, o);
            if (lane == 0) sc[s] = acc;
        }
        __syncthreads();
        if (tx == 0) {
            float mx = sc[0];
            for (int s = 1; s < SS; ++s) mx = fmaxf(mx, sc[s]);
            float sum = 0.f;
            for (int s = 0; s < SS; ++s) { float e = expf(sc[s] - mx); sc[s] = e; sum += e; }
            float inv = 1.f / sum;
            for (int s = 0; s < SS; ++s) sc[s] *= inv;
        }
        __syncthreads();
        if (tx < SS) p.atP[b * SS + tx] = sc[tx];
        // wc pass from fp16 ctx copy: thread tx owns k = 2*tx, 2*tx+1
        {
            const __half2* c2 = (const __half2*)p.atCtxH;
            float ax = 0.f, ay = 0.f;
#pragma unroll 8
            for (int s = 0; s < SS; ++s) {
                float2 cf = __half22float2(c2[(((size_t)s * BB + b) << 9) + tx]);
                ax += sc[s] * cf.x;
                ay += sc[s] * cf.y;
            }
            ((__half2*)p.atWc)[((size_t)b << 9) + tx] = __floats2half2_rn(ax, ay);
        }
    }
}

// ---------------- X0 precompute: emb[input] @ w_ih0^T + biases ----------
__global__ __launch_bounds__(512, 1) void x0_k(StepP p) {
    extern __shared__ __align__(16) char sm[];
    mgemm<false, false, true, 1>(p.l0, sm, blockIdx.y, blockIdx.x);
}

// ----------------------------- init kernels ----------------------------
__global__ void split_w(const float* __restrict__ w_ih, const float* __restrict__ w_hh,
                        const float* __restrict__ w_in, const float* __restrict__ w_out,
                        const float* __restrict__ ctx) {
    const size_t N = 24117248;
    for (size_t i = (size_t)blockIdx.x * 256 + threadIdx.x; i < N;
         i += (size_t)gridDim.x * 256) {
        if (i < 8388608) {
            g_Wih[i] = __float2half_rn(w_ih[i]);
        } else if (i < 16777216) {
            size_t j = i - 8388608; g_Whh[j] = __float2half_rn(w_hh[j]);
        } else if (i < 17825792) {
            size_t j = i - 16777216; g_Win[j] = __float2half_rn(w_in[j]);
        } else if (i < 19922944) {
            size_t j = i - 17825792; g_Wo[j] = __float2half_rn(w_out[j]);
        } else {
            size_t j = i - 19922944; g_ctxH[j] = __float2half_rn(ctx[j]);
        }
    }
}

__global__ void gather_xe(const int* __restrict__ inp, const float* __restrict__ emb) {
    size_t i = (size_t)blockIdx.x * 256 + threadIdx.x;
    if (i < 4194304) {
        size_t tb = i >> 10, k = i & 1023;
        float v = emb[(size_t)inp[tb] * 1024 + k];
        split2(v, g_XEh[i], g_XEl[i]);
    }
}

__global__ void init_sk(const float* __restrict__ h0, const float* __restrict__ c0) {
    int i = blockIdx.x * 256 + threadIdx.x;
    if (i < BH) {
        float a = h0[i], b = h0[BH + i];
        g_h0F[1][i] = a; g_h0H[1][i] = __float2half_rn(a);   // h0(-1): slot 1
        g_h1F[3][i] = b; g_h1H[3][i] = __float2half_rn(b);   // h1(-1): slot 3
        g_c0F[i] = c0[i];
        g_c1F[i] = c0[BH + i];
    }
}

__global__ void final_k(float* __restrict__ hf, float* __restrict__ cf,
                        float* __restrict__ at) {
    int i = blockIdx.x * 256 + threadIdx.x;
    if (i < BH) {
        hf[i] = g_h0F[1][i];            // h0(63): 63&1 = 1
        hf[BH + i] = g_h1F[3][i];       // h1(63): 63&3 = 3
        cf[i] = g_c0F[i];
        cf[BH + i] = g_c1F[i];
    }
    if (i < BB * SS) at[i] = g_attn[i];
}

// ------------------------------- launch --------------------------------
extern "C" void kernel_launch(void* const* d_in, const int* in_sizes, int n_in,
                              void* d_out, int out_size) {
    (void)in_sizes; (void)n_in; (void)out_size;
    const int*   inp   = (const int*)d_in[0];
    const float* h0    = (const float*)d_in[1];
    const float* c0    = (const float*)d_in[2];
    const float* ctx   = (const float*)d_in[3];
    const float* emb   = (const float*)d_in[4];
    const float* w_ih  = (const float*)d_in[5];
    const float* w_hh  = (const float*)d_in[6];
    const float* b_ih  = (const float*)d_in[7];
    const float* b_hh  = (const float*)d_in[8];
    const float* w_in  = (const float*)d_in[9];
    const float* w_out = (const float*)d_in[10];

    float* out  = (float*)d_out;
    float* outs = out;
    float* hf   = out + (size_t)TT * BH;
    float* cf   = hf + 2 * BH;
    float* at   = cf + 2 * BH;

    cudaFuncSetAttribute(step_k, cudaFuncAttributeMaxDynamicSharedMemorySize, SMB_STEP);
    cudaFuncSetAttribute(x0_k,   cudaFuncAttributeMaxDynamicSharedMemorySize, SMB_X0);

    h16 *Wih, *Whh, *Win, *Wo, *XEh, *XEl, *CtxH;
    h16 *h0H, *h1H, *wcH;
    float *h0F, *h1F, *c0F, *c1F, *qF, *X0, *AT;
    cudaGetSymbolAddress((void**)&Wih, g_Wih); cudaGetSymbolAddress((void**)&Whh, g_Whh);
    cudaGetSymbolAddress((void**)&Win, g_Win); cudaGetSymbolAddress((void**)&Wo,  g_Wo);
    cudaGetSymbolAddress((void**)&XEh, g_XEh); cudaGetSymbolAddress((void**)&XEl, g_XEl);
    cudaGetSymbolAddress((void**)&CtxH, g_ctxH);
    cudaGetSymbolAddress((void**)&h0F, g_h0F); cudaGetSymbolAddress((void**)&h1F, g_h1F);
    cudaGetSymbolAddress((void**)&h0H, g_h0H); cudaGetSymbolAddress((void**)&h1H, g_h1H);
    cudaGetSymbolAddress((void**)&c0F, g_c0F); cudaGetSymbolAddress((void**)&c1F, g_c1F);
    cudaGetSymbolAddress((void**)&qF,  g_qF);
    cudaGetSymbolAddress((void**)&wcH, g_wcH);
    cudaGetSymbolAddress((void**)&X0,  g_X0);
    cudaGetSymbolAddress((void**)&AT,  g_attn);

    split_w<<<16384, 256>>>(w_ih, w_hh, w_in, w_out, ctx);
    gather_xe<<<16384, 256>>>(inp, emb);
    init_sk<<<256, 256>>>(h0, c0);

    {   // X0 = XEh@W + XEl@W + biases, grid (32 nblk, 64 mblk), DUALA path
        StepP p = {};
        Seg& s = p.l0;
        s.A1 = XEh; s.A2 = XEl;
        s.W1 = Wih; s.wld = 1024; s.K = 1024;
        s.bias1 = b_ih; s.bias2 = b_hh;
        s.outC = X0; s.ldC = 4096; s.doTanh = 0;
        x0_k<<<dim3(32, 64), 512, SMB_X0>>>(p);
    }

    // Pipeline: launch k carries L1(k-1), OUT(k-4), L0(k), Q(k-2), ATTN(k-3).
    for (int k = 0; k <= 67; ++k) {
        StepP p = {};
        int tL1 = k - 1, tL0 = k, tQ = k - 2, tAt = k - 3, tOut = k - 4;
        if (tL1 >= 0 && tL1 < TT) {
            p.nL1 = 32;
            Seg& s = p.l1;
            s.A1 = h0H + (size_t)(tL1 & 1) * BH;
            s.A2 = h1H + (size_t)((tL1 - 1) & 3) * BH;
            s.W1 = Wih + 4194304;
            s.W2 = Whh + 4194304;
            s.wld = 1024; s.K = 2048;
            s.bias1 = b_ih + 4096; s.bias2 = b_hh + 4096;
            s.cSt = c1F;
            s.hF = h1F + (size_t)(tL1 & 3) * BH;
            s.hH = h1H + (size_t)(tL1 & 3) * BH;
        }
        if (tOut >= 0 && tOut < TT) {
            p.nOut = 8;
            Seg& s = p.o;
            s.A1 = wcH + (size_t)(tOut & 1) * BH;
            s.A2 = h1H + (size_t)(tOut & 3) * BH;
            s.W1 = Wo;
            s.W2 = Wo + 1024;
            s.wld = 2048; s.K = 2048;
            s.outC = outs + (size_t)tOut * BH; s.ldC = HH; s.doTanh = 1;
        }
        if (tL0 >= 0 && tL0 < TT) {
            p.nL0 = 32;
            Seg& s = p.l0;
            s.A1 = h0H + (size_t)((tL0 + 1) & 1) * BH;
            s.W1 = Whh; s.wld = 1024; s.K = 1024;
            s.addC = X0 + (size_t)tL0 * 64 * 4096;
            s.cSt = c0F;
            s.hF = h0F + (size_t)(tL0 & 1) * BH;
            s.hH = h0H + (size_t)(tL0 & 1) * BH;
        }
        if (tQ >= 0 && tQ < TT) {
            p.nQ = 8;
            Seg& s = p.q;
            s.A1 = h1H + (size_t)(tQ & 3) * BH;
            s.W1 = Win; s.wld = 1024; s.K = 1024;
            s.outC = qF + (size_t)(tQ & 1) * BH; s.ldC = HH; s.doTanh = 0;
        }
        if (tAt >= 0 && tAt < TT) {
            p.nAt = 64;
            p.atQ = qF + (size_t)(tAt & 1) * BH;
            p.atCtx = ctx;
            p.atCtxH = CtxH;
            p.atWc = wcH + (size_t)(tAt & 1) * BH;
            p.atP = AT;
        }
        int grid = p.nL1 + p.nOut + p.nL0 + p.nQ + p.nAt;
        if (grid > 0) step_k<<<grid, 512, SMB_STEP>>>(p);
    }

    final_k<<<512, 256>>>(hf, cf, at);
}

// round 14
// speedup vs baseline: 1.1577x; 1.1577x over previous
#include <cuda_runtime.h>
#include <cuda_fp16.h>
#include <cstdint>

// Decoder: 2-layer LSTM + Luong attention. T=B=S=64, H=E=1024, L=2.
// mma.sync fp16 (A/W single fp16; X0 precompute hi/lo A), 64x64 tiles,
// 512 threads = 4 warpgroups, 4-way K-split, k16 chunks, 4-stage pipeline.
// Block order [ATTN, OUT, L1, L0, Q] (R11-proven). Attention: fp32 scores,
// fp16-ctx weighted sum.

#define TT 64
#define BB 64
#define SS 64
#define HH 1024
#define BH (BB * HH)

typedef unsigned long long ull;
typedef __half h16;

__device__ __forceinline__ float sigm_(float x) { return 1.f / (1.f + expf(-x)); }
__device__ __forceinline__ void split2(float v, h16& hi, h16& lo) {
    hi = __float2half_rn(v);
    lo = __float2half_rn(v - __half2float(hi));
}

// ------------------------------- scratch -------------------------------
__device__ __align__(256) h16 g_Wih[8388608];      // [2][4096][1024]
__device__ __align__(256) h16 g_Whh[8388608];
__device__ __align__(256) h16 g_Win[1048576];
__device__ __align__(256) h16 g_Wo[2097152];       // [1024][2048]
__device__ __align__(256) h16 g_XEh[4194304], g_XEl[4194304];
__device__ __align__(256) h16 g_ctxH[4194304];     // fp16 copy of context
__device__ float g_X0[(size_t)4096 * 4096];        // [t*64+b][4096 gate cols]
__device__ float g_h0F[2][BH], g_h1F[4][BH], g_c0F[BH], g_c1F[BH];
__device__ __align__(256) h16 g_h0H[2][BH];
__device__ __align__(256) h16 g_h1H[4][BH];
__device__ __align__(256) h16 g_wcH[2][BH];
__device__ float g_qF[2][BH];
__device__ float g_attn[BB * SS];

// ----------------------------- ptx helpers -----------------------------
__device__ __forceinline__ uint32_t s2u(const void* p) {
    uint32_t a;
    asm("{ .reg .u64 t; cvta.to.shared.u64 t, %1; cvt.u32.u64 %0, t; }"
        : "=r"(a) : "l"(p));
    return a;
}
__device__ __forceinline__ void cpa16(uint32_t dst, const void* src) {
    asm volatile("cp.async.cg.shared.global [%0], [%1], 16;"
                 :: "r"(dst), "l"(src) : "memory");
}
__device__ __forceinline__ void ldsm4(uint32_t* r, uint32_t addr) {
    asm volatile("ldmatrix.sync.aligned.m8n8.x4.shared.b16 {%0,%1,%2,%3}, [%4];"
                 : "=r"(r[0]), "=r"(r[1]), "=r"(r[2]), "=r"(r[3]) : "r"(addr));
}
__device__ __forceinline__ void mma16816(float* d, const uint32_t* a, const uint32_t* b) {
    asm volatile(
        "mma.sync.aligned.m16n8k16.row.col.f32.f16.f16.f32 "
        "{%0,%1,%2,%3},{%4,%5,%6,%7},{%8,%9},{%0,%1,%2,%3};"
        : "+f"(d[0]), "+f"(d[1]), "+f"(d[2]), "+f"(d[3])
        : "r"(a[0]), "r"(a[1]), "r"(a[2]), "r"(a[3]), "r"(b[0]), "r"(b[1]));
}
__device__ __forceinline__ void barw(int wg) {
    asm volatile("bar.sync %0, 128;" :: "r"(wg + 1) : "memory");
}

// ---------------------------- GEMM segment -----------------------------
// C[64 m(batch), 64 n] = A @ W^T. 512 threads = 4 wgs of 128; each wg does
// a K-slice into a partial accumulator; combined in epilogue.
// DUALA: A hi/lo pair sharing one W load (X0 precompute only).
// GATE: n cols = 4 gates x 16 hidden units. PAIR2: K=2048 (wg pair = half).
struct Seg {
    const h16 *A1, *A2;
    const h16 *W1, *W2;
    int wld, K;
    const float *addC, *bias1, *bias2;
    float *cSt, *hF;
    h16 *hH;
    float *outC; int ldC, doTanh;
};

// per-wg stage (k16), rows 64 x 48B (32B data + 16B pad, conflict-free):
//   normal: A 3072 | W 3072            = 6144 B
//   DUALA : Ah 3072 | Al 3072 | W 3072 = 9216 B
#define SMB_STEP (4 * 4 * 6144)
#define SMB_X0   (4 * 4 * 9216)

template <bool GATE, bool PAIR2, bool DUALA, int EPI>
__device__ void mgemm(const Seg& a, char* sm, int mblk, int nblk) {
    const int STG  = DUALA ? 9216 : 6144;
    const int WOFF = DUALA ? 6144 : 3072;
    const int tx = threadIdx.x;
    const int wg = tx >> 7;              // warpgroup 0..3
    const int wtx = tx & 127;
    const int warp = wtx >> 5, lane = tx & 31;
    const int wm = warp << 4;            // warp m offset; n covers all 64
    const uint32_t smb = s2u(sm) + wg * (4 * STG);

    const int sr = wtx >> 1, su = wtx & 1;
    const int am = mblk * 64 + sr;
    const int wr = GATE ? ((sr >> 4) * HH + nblk * 16 + (sr & 15))
                        : (nblk * 64 + sr);

    const h16 *a1, *a2, *w1;
    int kbase, Kwg;
    if (PAIR2) {
        int p = wg >> 1;
        a1 = p ? a.A2 : a.A1;
        w1 = p ? a.W2 : a.W1;
        a2 = nullptr;
        kbase = (wg & 1) << 9; Kwg = 512;
    } else {
        a1 = a.A1; a2 = a.A2; w1 = a.W1;
        Kwg = a.K >> 2; kbase = wg * Kwg;
    }
    const size_t arow = (size_t)am * 1024;
    const size_t wrow = (size_t)wr * a.wld;

    float acc[8][4] = {};
    const int nc = Kwg >> 4;             // k16 chunks

    const uint32_t aoff = (uint32_t)((wm + (lane & 15)) * 48 + ((lane >> 4) << 4));
    const uint32_t boff = (uint32_t)(((((lane >> 4) << 3) + (lane & 7))) * 48
                                     + (((lane >> 3) & 1) << 4));

#define STAGE(c)                                                               \
    {                                                                          \
        int kl = kbase + ((c) << 4);                                           \
        uint32_t db = smb + ((c) & 3) * STG + sr * 48 + (su << 4);             \
        cpa16(db, a1 + arow + kl + su * 8);                                    \
        if (DUALA) cpa16(db + 3072, a2 + arow + kl + su * 8);                  \
        cpa16(db + WOFF, w1 + wrow + kl + su * 8);                             \
        asm volatile("cp.async.commit_group;" ::: "memory");                   \
    }

    STAGE(0) STAGE(1) STAGE(2)
    for (int c = 0; c < nc; ++c) {
        if (c + 3 < nc) {
            asm volatile("cp.async.wait_group 2;" ::: "memory");
            barw(wg);
            STAGE(c + 3)
        } else {
            asm volatile("cp.async.wait_group 0;" ::: "memory");
            barw(wg);
        }
        const uint32_t base = smb + (c & 3) * STG;
        uint32_t ah[4], al[4], bw[16];
        ldsm4(ah, base + aoff);
        if (DUALA) ldsm4(al, base + 3072 + aoff);
#pragma unroll
        for (int j = 0; j < 4; ++j)
            ldsm4(bw + 4 * j, base + WOFF + boff + j * 16 * 48);
#pragma unroll
        for (int nt = 0; nt < 8; ++nt) {
            mma16816(acc[nt], ah, bw + 2 * nt);
            if (DUALA) mma16816(acc[nt], al, bw + 2 * nt);
        }
    }
#undef STAGE
    __syncthreads();

    float* St = (float*)sm;
    float* Sw = St + wg * 4224;          // 64*66
    const int rr = wm + (lane >> 2);
#pragma unroll
    for (int nt = 0; nt < 8; ++nt) {
        int cc = nt * 8 + ((lane & 3) << 1);
        Sw[cc * 66 + rr]           = acc[nt][0];
        Sw[(cc + 1) * 66 + rr]     = acc[nt][1];
        Sw[cc * 66 + rr + 8]       = acc[nt][2];
        Sw[(cc + 1) * 66 + rr + 8] = acc[nt][3];
    }
    __syncthreads();

    if (EPI == 0) {      // fused LSTM cell
#pragma unroll
        for (int it = 0; it < 2; ++it) {
            int idx = tx + it * 512;
            int b = idx & 63, jj = idx >> 6;
            int jg = nblk * 16 + jj;
            float gi = St[jj * 66 + b]        + St[4224 + jj * 66 + b]
                     + St[8448 + jj * 66 + b] + St[12672 + jj * 66 + b];
            float gf = St[(16 + jj) * 66 + b]        + St[4224 + (16 + jj) * 66 + b]
                     + St[8448 + (16 + jj) * 66 + b] + St[12672 + (16 + jj) * 66 + b];
            float gg = St[(32 + jj) * 66 + b]        + St[4224 + (32 + jj) * 66 + b]
                     + St[8448 + (32 + jj) * 66 + b] + St[12672 + (32 + jj) * 66 + b];
            float go = St[(48 + jj) * 66 + b]        + St[4224 + (48 + jj) * 66 + b]
                     + St[8448 + (48 + jj) * 66 + b] + St[12672 + (48 + jj) * 66 + b];
            if (a.addC) {
                const float* ac = a.addC + (size_t)b * 4096 + jg;
                gi += ac[0]; gf += ac[1024]; gg += ac[2048]; go += ac[3072];
            }
            if (a.bias1) {
                gi += a.bias1[jg] + a.bias2[jg];
                gf += a.bias1[1024 + jg] + a.bias2[1024 + jg];
                gg += a.bias1[2048 + jg] + a.bias2[2048 + jg];
                go += a.bias1[3072 + jg] + a.bias2[3072 + jg];
            }
            float cc2 = sigm_(gf) * a.cSt[b * HH + jg] + sigm_(gi) * tanhf(gg);
            a.cSt[b * HH + jg] = cc2;
            float h = sigm_(go) * tanhf(cc2);
            a.hF[b * HH + jg] = h;
            a.hH[b * HH + jg] = __float2half_rn(h);
        }
    } else {             // plain store (optional bias / tanh)
#pragma unroll
        for (int it = 0; it < 8; ++it) {
            int idx = tx + it * 512;
            int row = idx >> 6, col = idx & 63;
            float v = St[col * 66 + row]        + St[4224 + col * 66 + row]
                    + St[8448 + col * 66 + row] + St[12672 + col * 66 + row];
            int cg = nblk * 64 + col;
            if (a.bias1) v += a.bias1[cg] + a.bias2[cg];
            if (a.doTanh) v = tanhf(v);
            a.outC[(size_t)(mblk * 64 + row) * a.ldC + cg] = v;
        }
    }
}

// ------------------------------ step kernel ----------------------------
// Block order [ATTN, OUT, L1, L0, Q] (R11-proven placement).
struct StepP {
    int nL1, nOut, nL0, nQ, nAt;
    Seg l1, o, l0, q;
    const float *atQ, *atCtx;
    const h16 *atCtxH;
    h16 *atWc;
    float* atP;
};

__global__ __launch_bounds__(512, 1) void step_k(StepP p) {
    extern __shared__ __align__(16) char sm[];
    const int bid = blockIdx.x;
    const int r0 = p.nAt, r1 = r0 + p.nOut, r2 = r1 + p.nL1, r3 = r2 + p.nL0;

    if (bid >= r0 && bid < r1) {
        mgemm<false, true, false, 1>(p.o, sm, 0, bid - r0);
    } else if (bid >= r1 && bid < r2) {
        mgemm<true, true, false, 0>(p.l1, sm, 0, bid - r1);
    } else if (bid >= r2 && bid < r3) {
        mgemm<true, false, false, 0>(p.l0, sm, 0, bid - r2);
    } else if (bid >= r3) {
        mgemm<false, false, false, 1>(p.q, sm, 0, bid - r3);
    } else {                              // ATTN: one block per batch b
        int b = bid;
        float* qs = (float*)sm;           // 1024 floats
        float* sc = qs + 1024;            // 64 floats
        const int tx = threadIdx.x;
        *(float2*)&qs[tx * 2] = *(const float2*)&p.atQ[(size_t)b * HH + tx * 2];
        __syncthreads();
        const int wid = tx >> 5, lane = tx & 31;
        for (int s = wid; s < SS; s += 16) {
            const float* cp = p.atCtx + ((size_t)s * BB + b) * HH;
            float acc = 0.f;
#pragma unroll
            for (int i = 0; i < 8; ++i) {
                float4 c4 = *(const float4*)(cp + i * 128 + lane * 4);
                float4 q4 = *(const float4*)&qs[i * 128 + lane * 4];
                acc += c4.x * q4.x + c4.y * q4.y + c4.z * q4.z + c4.w * q4.w;
            }
#pragma unroll
            for (int o = 16; o; o >>= 1) acc += __shfl_down_sync(0xFFFFFFFFu, acc, o);
            if (lane == 0) sc[s] = acc;
        }
        __syncthreads();
        if (tx == 0) {
            float mx = sc[0];
            for (int s = 1; s < SS; ++s) mx = fmaxf(mx, sc[s]);
            float sum = 0.f;
            for (int s = 0; s < SS; ++s) { float e = expf(sc[s] - mx); sc[s] = e; sum += e; }
            float inv = 1.f / sum;
            for (int s = 0; s < SS; ++s) sc[s] *= inv;
        }
        __syncthreads();
        if (tx < SS) p.atP[b * SS + tx] = sc[tx];
        // wc pass from fp16 ctx copy: thread tx owns k = 2*tx, 2*tx+1
        {
            const __half2* c2 = (const __half2*)p.atCtxH;
            float ax = 0.f, ay = 0.f;
#pragma unroll 8
            for (int s = 0; s < SS; ++s) {
                float2 cf = __half22float2(c2[(((size_t)s * BB + b) << 9) + tx]);
                ax += sc[s] * cf.x;
                ay += sc[s] * cf.y;
            }
            ((__half2*)p.atWc)[((size_t)b << 9) + tx] = __floats2half2_rn(ax, ay);
        }
    }
}

// ---------------- X0 precompute: emb[input] @ w_ih0^T + biases ----------
__global__ __launch_bounds__(512, 1) void x0_k(StepP p) {
    extern __shared__ __align__(16) char sm[];
    mgemm<false, false, true, 1>(p.l0, sm, blockIdx.y, blockIdx.x);
}

// ----------------------------- init kernels ----------------------------
__global__ void split_w(const float* __restrict__ w_ih, const float* __restrict__ w_hh,
                        const float* __restrict__ w_in, const float* __restrict__ w_out,
                        const float* __restrict__ ctx) {
    const size_t N = 24117248;
    for (size_t i = (size_t)blockIdx.x * 256 + threadIdx.x; i < N;
         i += (size_t)gridDim.x * 256) {
        if (i < 8388608) {
            g_Wih[i] = __float2half_rn(w_ih[i]);
        } else if (i < 16777216) {
            size_t j = i - 8388608; g_Whh[j] = __float2half_rn(w_hh[j]);
        } else if (i < 17825792) {
            size_t j = i - 16777216; g_Win[j] = __float2half_rn(w_in[j]);
        } else if (i < 19922944) {
            size_t j = i - 17825792; g_Wo[j] = __float2half_rn(w_out[j]);
        } else {
            size_t j = i - 19922944; g_ctxH[j] = __float2half_rn(ctx[j]);
        }
    }
}

__global__ void gather_xe(const int* __restrict__ inp, const float* __restrict__ emb) {
    size_t i = (size_t)blockIdx.x * 256 + threadIdx.x;
    if (i < 4194304) {
        size_t tb = i >> 10, k = i & 1023;
        float v = emb[(size_t)inp[tb] * 1024 + k];
        split2(v, g_XEh[i], g_XEl[i]);
    }
}

__global__ void init_sk(const float* __restrict__ h0, const float* __restrict__ c0) {
    int i = blockIdx.x * 256 + threadIdx.x;
    if (i < BH) {
        float a = h0[i], b = h0[BH + i];
        g_h0F[1][i] = a; g_h0H[1][i] = __float2half_rn(a);   // h0(-1): slot 1
        g_h1F[3][i] = b; g_h1H[3][i] = __float2half_rn(b);   // h1(-1): slot 3
        g_c0F[i] = c0[i];
        g_c1F[i] = c0[BH + i];
    }
}

__global__ void final_k(float* __restrict__ hf, float* __restrict__ cf,
                        float* __restrict__ at) {
    int i = blockIdx.x * 256 + threadIdx.x;
    if (i < BH) {
        hf[i] = g_h0F[1][i];            // h0(63): 63&1 = 1
        hf[BH + i] = g_h1F[3][i];       // h1(63): 63&3 = 3
        cf[i] = g_c0F[i];
        cf[BH + i] = g_c1F[i];
    }
    if (i < BB * SS) at[i] = g_attn[i];
}

// ------------------------------- launch --------------------------------
extern "C" void kernel_launch(void* const* d_in, const int* in_sizes, int n_in,
                              void* d_out, int out_size) {
    (void)in_sizes; (void)n_in; (void)out_size;
    const int*   inp   = (const int*)d_in[0];
    const float* h0    = (const float*)d_in[1];
    const float* c0    = (const float*)d_in[2];
    const float* ctx   = (const float*)d_in[3];
    const float* emb   = (const float*)d_in[4];
    const float* w_ih  = (const float*)d_in[5];
    const float* w_hh  = (const float*)d_in[6];
    const float* b_ih  = (const float*)d_in[7];
    const float* b_hh  = (const float*)d_in[8];
    const float* w_in  = (const float*)d_in[9];
    const float* w_out = (const float*)d_in[10];

    float* out  = (float*)d_out;
    float* outs = out;
    float* hf   = out + (size_t)TT * BH;
    float* cf   = hf + 2 * BH;
    float* at   = cf + 2 * BH;

    cudaFuncSetAttribute(step_k, cudaFuncAttributeMaxDynamicSharedMemorySize, SMB_STEP);
    cudaFuncSetAttribute(x0_k,   cudaFuncAttributeMaxDynamicSharedMemorySize, SMB_X0);

    h16 *Wih, *Whh, *Win, *Wo, *XEh, *XEl, *CtxH;
    h16 *h0H, *h1H, *wcH;
    float *h0F, *h1F, *c0F, *c1F, *qF, *X0, *AT;
    cudaGetSymbolAddress((void**)&Wih, g_Wih); cudaGetSymbolAddress((void**)&Whh, g_Whh);
    cudaGetSymbolAddress((void**)&Win, g_Win); cudaGetSymbolAddress((void**)&Wo,  g_Wo);
    cudaGetSymbolAddress((void**)&XEh, g_XEh); cudaGetSymbolAddress((void**)&XEl, g_XEl);
    cudaGetSymbolAddress((void**)&CtxH, g_ctxH);
    cudaGetSymbolAddress((void**)&h0F, g_h0F); cudaGetSymbolAddress((void**)&h1F, g_h1F);
    cudaGetSymbolAddress((void**)&h0H, g_h0H); cudaGetSymbolAddress((void**)&h1H, g_h1H);
    cudaGetSymbolAddress((void**)&c0F, g_c0F); cudaGetSymbolAddress((void**)&c1F, g_c1F);
    cudaGetSymbolAddress((void**)&qF,  g_qF);
    cudaGetSymbolAddress((void**)&wcH, g_wcH);
    cudaGetSymbolAddress((void**)&X0,  g_X0);
    cudaGetSymbolAddress((void**)&AT,  g_attn);

    split_w<<<16384, 256>>>(w_ih, w_hh, w_in, w_out, ctx);
    gather_xe<<<16384, 256>>>(inp, emb);
    init_sk<<<256, 256>>>(h0, c0);

    {   // X0 = XEh@W + XEl@W + biases, grid (64 nblk, 64 mblk), DUALA path
        StepP p = {};
        Seg& s = p.l0;
        s.A1 = XEh; s.A2 = XEl;
        s.W1 = Wih; s.wld = 1024; s.K = 1024;
        s.bias1 = b_ih; s.bias2 = b_hh;
        s.outC = X0; s.ldC = 4096; s.doTanh = 0;
        x0_k<<<dim3(64, 64), 512, SMB_X0>>>(p);
    }

    // Pipeline: launch k carries L1(k-1), OUT(k-4), L0(k), Q(k-2), ATTN(k-3).
    for (int k = 0; k <= 67; ++k) {
        StepP p = {};
        int tL1 = k - 1, tL0 = k, tQ = k - 2, tAt = k - 3, tOut = k - 4;
        if (tL1 >= 0 && tL1 < TT) {
            p.nL1 = 64;
            Seg& s = p.l1;
            s.A1 = h0H + (size_t)(tL1 & 1) * BH;
            s.A2 = h1H + (size_t)((tL1 - 1) & 3) * BH;
            s.W1 = Wih + 4194304;
            s.W2 = Whh + 4194304;
            s.wld = 1024; s.K = 2048;
            s.bias1 = b_ih + 4096; s.bias2 = b_hh + 4096;
            s.cSt = c1F;
            s.hF = h1F + (size_t)(tL1 & 3) * BH;
            s.hH = h1H + (size_t)(tL1 & 3) * BH;
        }
        if (tOut >= 0 && tOut < TT) {
            p.nOut = 16;
            Seg& s = p.o;
            s.A1 = wcH + (size_t)(tOut & 1) * BH;
            s.A2 = h1H + (size_t)(tOut & 3) * BH;
            s.W1 = Wo;
            s.W2 = Wo + 1024;
            s.wld = 2048; s.K = 2048;
            s.outC = outs + (size_t)tOut * BH; s.ldC = HH; s.doTanh = 1;
        }
        if (tL0 >= 0 && tL0 < TT) {
            p.nL0 = 64;
            Seg& s = p.l0;
            s.A1 = h0H + (size_t)((tL0 + 1) & 1) * BH;
            s.W1 = Whh; s.wld = 1024; s.K = 1024;
            s.addC = X0 + (size_t)tL0 * 64 * 4096;
            s.cSt = c0F;
            s.hF = h0F + (size_t)(tL0 & 1) * BH;
            s.hH = h0H + (size_t)(tL0 & 1) * BH;
        }
        if (tQ >= 0 && tQ < TT) {
            p.nQ = 16;
            Seg& s = p.q;
            s.A1 = h1H + (size_t)(tQ & 3) * BH;
            s.W1 = Win; s.wld = 1024; s.K = 1024;
            s.outC = qF + (size_t)(tQ & 1) * BH; s.ldC = HH; s.doTanh = 0;
        }
        if (tAt >= 0 && tAt < TT) {
            p.nAt = 64;
            p.atQ = qF + (size_t)(tAt & 1) * BH;
            p.atCtx = ctx;
            p.atCtxH = CtxH;
            p.atWc = wcH + (size_t)(tAt & 1) * BH;
            p.atP = AT;
        }
        int grid = p.nL1 + p.nOut + p.nL0 + p.nQ + p.nAt;
        if (grid > 0) step_k<<<grid, 512, SMB_STEP>>>(p);
    }

    final_k<<<512, 256>>>(hf, cf, at);
}

// round 15
// speedup vs baseline: 1.2445x; 1.0750x over previous
#include <cuda_runtime.h>
#include <cuda_fp16.h>
#include <cstdint>

// Decoder: 2-layer LSTM + Luong attention. T=B=S=64, H=E=1024, L=2.
// Step path: R11-proven (mma.sync fp16, 64x64 tiles, 4 warpgroups, 4-way
// K-split, k16 chunks, 4-stage pipeline, fp32 two-pass attention).
// X0 precompute: merged 64x128 tile (R13-proven, A loaded once).

#define TT 64
#define BB 64
#define SS 64
#define HH 1024
#define BH (BB * HH)

typedef unsigned long long ull;
typedef __half h16;

__device__ __forceinline__ float sigm_(float x) { return 1.f / (1.f + expf(-x)); }
__device__ __forceinline__ void split2(float v, h16& hi, h16& lo) {
    hi = __float2half_rn(v);
    lo = __float2half_rn(v - __half2float(hi));
}

// ------------------------------- scratch -------------------------------
__device__ __align__(256) h16 g_Wih[8388608];      // [2][4096][1024]
__device__ __align__(256) h16 g_Whh[8388608];
__device__ __align__(256) h16 g_Win[1048576];
__device__ __align__(256) h16 g_Wo[2097152];       // [1024][2048]
__device__ __align__(256) h16 g_XEh[4194304], g_XEl[4194304];
__device__ float g_X0[(size_t)4096 * 4096];        // [t*64+b][4096 gate cols]
__device__ float g_h0F[2][BH], g_h1F[4][BH], g_c0F[BH], g_c1F[BH];
__device__ __align__(256) h16 g_h0H[2][BH];
__device__ __align__(256) h16 g_h1H[4][BH];
__device__ __align__(256) h16 g_wcH[2][BH];
__device__ float g_qF[2][BH];
__device__ float g_attn[BB * SS];

// ----------------------------- ptx helpers -----------------------------
__device__ __forceinline__ uint32_t s2u(const void* p) {
    uint32_t a;
    asm("{ .reg .u64 t; cvta.to.shared.u64 t, %1; cvt.u32.u64 %0, t; }"
        : "=r"(a) : "l"(p));
    return a;
}
__device__ __forceinline__ void cpa16(uint32_t dst, const void* src) {
    asm volatile("cp.async.cg.shared.global [%0], [%1], 16;"
                 :: "r"(dst), "l"(src) : "memory");
}
__device__ __forceinline__ void ldsm4(uint32_t* r, uint32_t addr) {
    asm volatile("ldmatrix.sync.aligned.m8n8.x4.shared.b16 {%0,%1,%2,%3}, [%4];"
                 : "=r"(r[0]), "=r"(r[1]), "=r"(r[2]), "=r"(r[3]) : "r"(addr));
}
__device__ __forceinline__ void mma16816(float* d, const uint32_t* a, const uint32_t* b) {
    asm volatile(
        "mma.sync.aligned.m16n8k16.row.col.f32.f16.f16.f32 "
        "{%0,%1,%2,%3},{%4,%5,%6,%7},{%8,%9},{%0,%1,%2,%3};"
        : "+f"(d[0]), "+f"(d[1]), "+f"(d[2]), "+f"(d[3])
        : "r"(a[0]), "r"(a[1]), "r"(a[2]), "r"(a[3]), "r"(b[0]), "r"(b[1]));
}
__device__ __forceinline__ void barw(int wg) {
    asm volatile("bar.sync %0, 128;" :: "r"(wg + 1) : "memory");
}

// ---------------------------- GEMM segment -----------------------------
// C[64 m(batch), 64 n] = A @ W^T. 512 threads = 4 wgs of 128; each wg does
// a K-slice into a partial accumulator; combined in epilogue.
// GATE: n cols = 4 gates x 16 hidden units. PAIR2: K=2048 (wg pair = half).
struct Seg {
    const h16 *A1, *A2;
    const h16 *W1, *W2;
    int wld, K;
    const float *addC, *bias1, *bias2;
    float *cSt, *hF;
    h16 *hH;
    float *outC; int ldC, doTanh;
};

// per-wg stage (k16), rows 64 x 48B (32B data + 16B pad, conflict-free):
//   step: A 3072 | W 3072 = 6144 B
//   x0 (merged 128n, DUALA): Ah 3072 | Al 3072 | W 6144 = 12288 B
#define SMB_STEP (4 * 4 * 6144)
#define SMB_X0   (4 * 4 * 12288)

template <bool GATE, bool PAIR2, int EPI>
__device__ void mgemm(const Seg& a, char* sm, int mblk, int nblk) {
    const int STG  = 6144;
    const int WOFF = 3072;
    const int tx = threadIdx.x;
    const int wg = tx >> 7;              // warpgroup 0..3
    const int wtx = tx & 127;
    const int warp = wtx >> 5, lane = tx & 31;
    const int wm = warp << 4;            // warp m offset; n covers all 64
    const uint32_t smb = s2u(sm) + wg * (4 * STG);

    const int sr = wtx >> 1, su = wtx & 1;
    const int am = mblk * 64 + sr;
    const int wr = GATE ? ((sr >> 4) * HH + nblk * 16 + (sr & 15))
                        : (nblk * 64 + sr);

    const h16 *a1, *w1;
    int kbase, Kwg;
    if (PAIR2) {
        int p = wg >> 1;
        a1 = p ? a.A2 : a.A1;
        w1 = p ? a.W2 : a.W1;
        kbase = (wg & 1) << 9; Kwg = 512;
    } else {
        a1 = a.A1; w1 = a.W1;
        Kwg = a.K >> 2; kbase = wg * Kwg;
    }
    const size_t arow = (size_t)am * 1024;
    const size_t wrow = (size_t)wr * a.wld;

    float acc[8][4] = {};
    const int nc = Kwg >> 4;             // k16 chunks

    const uint32_t aoff = (uint32_t)((wm + (lane & 15)) * 48 + ((lane >> 4) << 4));
    const uint32_t boff = (uint32_t)(((((lane >> 4) << 3) + (lane & 7))) * 48
                                     + (((lane >> 3) & 1) << 4));

#define STAGE(c)                                                               \
    {                                                                          \
        int kl = kbase + ((c) << 4);                                           \
        uint32_t db = smb + ((c) & 3) * STG + sr * 48 + (su << 4);             \
        cpa16(db, a1 + arow + kl + su * 8);                                    \
        cpa16(db + WOFF, w1 + wrow + kl + su * 8);                             \
        asm volatile("cp.async.commit_group;" ::: "memory");                   \
    }

    STAGE(0) STAGE(1) STAGE(2)
    for (int c = 0; c < nc; ++c) {
        if (c + 3 < nc) {
            asm volatile("cp.async.wait_group 2;" ::: "memory");
            barw(wg);
            STAGE(c + 3)
        } else {
            asm volatile("cp.async.wait_group 0;" ::: "memory");
            barw(wg);
        }
        const uint32_t base = smb + (c & 3) * STG;
        uint32_t ah[4], bw[16];
        ldsm4(ah, base + aoff);
#pragma unroll
        for (int j = 0; j < 4; ++j)
            ldsm4(bw + 4 * j, base + WOFF + boff + j * 16 * 48);
#pragma unroll
        for (int nt = 0; nt < 8; ++nt)
            mma16816(acc[nt], ah, bw + 2 * nt);
    }
#undef STAGE
    __syncthreads();

    float* St = (float*)sm;
    float* Sw = St + wg * 4224;          // 64*66
    const int rr = wm + (lane >> 2);
#pragma unroll
    for (int nt = 0; nt < 8; ++nt) {
        int cc = nt * 8 + ((lane & 3) << 1);
        Sw[cc * 66 + rr]           = acc[nt][0];
        Sw[(cc + 1) * 66 + rr]     = acc[nt][1];
        Sw[cc * 66 + rr + 8]       = acc[nt][2];
        Sw[(cc + 1) * 66 + rr + 8] = acc[nt][3];
    }
    __syncthreads();

    if (EPI == 0) {      // fused LSTM cell
#pragma unroll
        for (int it = 0; it < 2; ++it) {
            int idx = tx + it * 512;
            int b = idx & 63, jj = idx >> 6;
            int jg = nblk * 16 + jj;
            float gi = St[jj * 66 + b]        + St[4224 + jj * 66 + b]
                     + St[8448 + jj * 66 + b] + St[12672 + jj * 66 + b];
            float gf = St[(16 + jj) * 66 + b]        + St[4224 + (16 + jj) * 66 + b]
                     + St[8448 + (16 + jj) * 66 + b] + St[12672 + (16 + jj) * 66 + b];
            float gg = St[(32 + jj) * 66 + b]        + St[4224 + (32 + jj) * 66 + b]
                     + St[8448 + (32 + jj) * 66 + b] + St[12672 + (32 + jj) * 66 + b];
            float go = St[(48 + jj) * 66 + b]        + St[4224 + (48 + jj) * 66 + b]
                     + St[8448 + (48 + jj) * 66 + b] + St[12672 + (48 + jj) * 66 + b];
            if (a.addC) {
                const float* ac = a.addC + (size_t)b * 4096 + jg;
                gi += ac[0]; gf += ac[1024]; gg += ac[2048]; go += ac[3072];
            }
            if (a.bias1) {
                gi += a.bias1[jg] + a.bias2[jg];
                gf += a.bias1[1024 + jg] + a.bias2[1024 + jg];
                gg += a.bias1[2048 + jg] + a.bias2[2048 + jg];
                go += a.bias1[3072 + jg] + a.bias2[3072 + jg];
            }
            float cc2 = sigm_(gf) * a.cSt[b * HH + jg] + sigm_(gi) * tanhf(gg);
            a.cSt[b * HH + jg] = cc2;
            float h = sigm_(go) * tanhf(cc2);
            a.hF[b * HH + jg] = h;
            a.hH[b * HH + jg] = __float2half_rn(h);
        }
    } else {             // plain store (optional bias / tanh)
#pragma unroll
        for (int it = 0; it < 8; ++it) {
            int idx = tx + it * 512;
            int row = idx >> 6, col = idx & 63;
            float v = St[col * 66 + row]        + St[4224 + col * 66 + row]
                    + St[8448 + col * 66 + row] + St[12672 + col * 66 + row];
            int cg = nblk * 64 + col;
            if (a.bias1) v += a.bias1[cg] + a.bias2[cg];
            if (a.doTanh) v = tanhf(v);
            a.outC[(size_t)(mblk * 64 + row) * a.ldC + cg] = v;
        }
    }
}

// -------------- X0 merged GEMM: C[64m,128n] = (Ah+Al) @ W^T --------------
// DUALA, 4-way K-split (K=1024, 256/wg), store + bias epilogue.
__device__ void xgemm(const Seg& a, char* sm, int mblk, int nblk) {
    const int STG = 12288;
    const int tx = threadIdx.x;
    const int wg = tx >> 7;
    const int wtx = tx & 127;
    const int warp = wtx >> 5, lane = tx & 31;
    const int wm = warp << 4;
    const uint32_t smb = s2u(sm) + wg * (4 * STG);

    const int sr = wtx >> 1, su = wtx & 1;
    const int am = mblk * 64 + sr;
    const int wrA = nblk * 128 + sr;
    const int wrB = nblk * 128 + sr + 64;

    const h16 *a1 = a.A1, *a2 = a.A2, *w1 = a.W1;
    const int Kwg = a.K >> 2, kbase = wg * Kwg;
    const size_t arow = (size_t)am * 1024;
    const size_t wroA = (size_t)wrA * a.wld;
    const size_t wroB = (size_t)wrB * a.wld;

    float acc[16][4] = {};
    const int nc = Kwg >> 4;

    const uint32_t aoff = (uint32_t)((wm + (lane & 15)) * 48 + ((lane >> 4) << 4));
    const uint32_t boff = (uint32_t)(((((lane >> 4) << 3) + (lane & 7))) * 48
                                     + (((lane >> 3) & 1) << 4));

#define XSTAGE(c)                                                              \
    {                                                                          \
        int kl = kbase + ((c) << 4);                                           \
        uint32_t db = smb + ((c) & 3) * STG;                                   \
        uint32_t ro = sr * 48 + (su << 4);                                     \
        cpa16(db + ro, a1 + arow + kl + su * 8);                               \
        cpa16(db + 3072 + ro, a2 + arow + kl + su * 8);                        \
        cpa16(db + 6144 + ro, w1 + wroA + kl + su * 8);                        \
        cpa16(db + 6144 + ro + 64 * 48, w1 + wroB + kl + su * 8);              \
        asm volatile("cp.async.commit_group;" ::: "memory");                   \
    }

    XSTAGE(0) XSTAGE(1) XSTAGE(2)
    for (int c = 0; c < nc; ++c) {
        if (c + 3 < nc) {
            asm volatile("cp.async.wait_group 2;" ::: "memory");
            barw(wg);
            XSTAGE(c + 3)
        } else {
            asm volatile("cp.async.wait_group 0;" ::: "memory");
            barw(wg);
        }
        const uint32_t base = smb + (c & 3) * STG;
        uint32_t ah[4], al[4], bw[32];
        ldsm4(ah, base + aoff);
        ldsm4(al, base + 3072 + aoff);
#pragma unroll
        for (int j = 0; j < 8; ++j)
            ldsm4(bw + 4 * j, base + 6144 + boff + j * 16 * 48);
#pragma unroll
        for (int nt = 0; nt < 16; ++nt) {
            mma16816(acc[nt], ah, bw + 2 * nt);
            mma16816(acc[nt], al, bw + 2 * nt);
        }
    }
#undef XSTAGE
    __syncthreads();

    float* St = (float*)sm;
    float* Sw = St + wg * 8448;
    const int rr = wm + (lane >> 2);
#pragma unroll
    for (int nt = 0; nt < 16; ++nt) {
        int cc = nt * 8 + ((lane & 3) << 1);
        Sw[cc * 66 + rr]           = acc[nt][0];
        Sw[(cc + 1) * 66 + rr]     = acc[nt][1];
        Sw[cc * 66 + rr + 8]       = acc[nt][2];
        Sw[(cc + 1) * 66 + rr + 8] = acc[nt][3];
    }
    __syncthreads();

#pragma unroll
    for (int it = 0; it < 16; ++it) {
        int idx = tx + it * 512;
        int row = idx >> 7, col = idx & 127;
        float v = St[col * 66 + row]         + St[8448 + col * 66 + row]
                + St[16896 + col * 66 + row] + St[25344 + col * 66 + row];
        int cg = nblk * 128 + col;
        v += a.bias1[cg] + a.bias2[cg];
        a.outC[(size_t)(mblk * 64 + row) * a.ldC + cg] = v;
    }
}

// ------------------------------ step kernel ----------------------------
// Block order [ATTN, OUT, L1, L0, Q] (R11-proven placement).
struct StepP {
    int nL1, nOut, nL0, nQ, nAt;
    Seg l1, o, l0, q;
    const float *atQ, *atCtx;
    h16 *atWc;
    float* atP;
};

__global__ __launch_bounds__(512, 1) void step_k(StepP p) {
    extern __shared__ __align__(16) char sm[];
    const int bid = blockIdx.x;
    const int r0 = p.nAt, r1 = r0 + p.nOut, r2 = r1 + p.nL1, r3 = r2 + p.nL0;

    if (bid >= r0 && bid < r1) {
        mgemm<false, true, 1>(p.o, sm, 0, bid - r0);
    } else if (bid >= r1 && bid < r2) {
        mgemm<true, true, 0>(p.l1, sm, 0, bid - r1);
    } else if (bid >= r2 && bid < r3) {
        mgemm<true, false, 0>(p.l0, sm, 0, bid - r2);
    } else if (bid >= r3) {
        mgemm<false, false, 1>(p.q, sm, 0, bid - r3);
    } else {                              // ATTN: one block per batch b
        int b = bid;
        float* qs = (float*)sm;           // 1024 floats
        float* sc = qs + 1024;            // 64 floats
        const int tx = threadIdx.x;
        *(float2*)&qs[tx * 2] = *(const float2*)&p.atQ[(size_t)b * HH + tx * 2];
        __syncthreads();
        const int wid = tx >> 5, lane = tx & 31;
        for (int s = wid; s < SS; s += 16) {
            const float* cp = p.atCtx + ((size_t)s * BB + b) * HH;
            float acc = 0.f;
#pragma unroll
            for (int i = 0; i < 8; ++i) {
                float4 c4 = *(const float4*)(cp + i * 128 + lane * 4);
                float4 q4 = *(const float4*)&qs[i * 128 + lane * 4];
                acc += c4.x * q4.x + c4.y * q4.y + c4.z * q4.z + c4.w * q4.w;
            }
#pragma unroll
            for (int o = 16; o; o >>= 1) acc += __shfl_down_sync(0xFFFFFFFFu, acc, o);
            if (lane == 0) sc[s] = acc;
        }
        __syncthreads();
        if (tx == 0) {
            float mx = sc[0];
            for (int s = 1; s < SS; ++s) mx = fmaxf(mx, sc[s]);
            float sum = 0.f;
            for (int s = 0; s < SS; ++s) { float e = expf(sc[s] - mx); sc[s] = e; sum += e; }
            float inv = 1.f / sum;
            for (int s = 0; s < SS; ++s) sc[s] *= inv;
        }
        __syncthreads();
        if (tx < SS) p.atP[b * SS + tx] = sc[tx];
        for (int k = tx; k < HH; k += 512) {
            float acc = 0.f;
#pragma unroll 8
            for (int s = 0; s < SS; ++s)
                acc += sc[s] * p.atCtx[((size_t)s * BB + b) * HH + k];
            p.atWc[(size_t)b * HH + k] = __float2half_rn(acc);
        }
    }
}

// ---------------- X0 precompute: emb[input] @ w_ih0^T + biases ----------
__global__ __launch_bounds__(512, 1) void x0_k(StepP p) {
    extern __shared__ __align__(16) char sm[];
    xgemm(p.l0, sm, blockIdx.y, blockIdx.x);
}

// ----------------------------- init kernels ----------------------------
__global__ void split_w(const float* __restrict__ w_ih, const float* __restrict__ w_hh,
                        const float* __restrict__ w_in, const float* __restrict__ w_out) {
    const size_t N = 19922944;
    for (size_t i = (size_t)blockIdx.x * 256 + threadIdx.x; i < N;
         i += (size_t)gridDim.x * 256) {
        if (i < 8388608) {
            g_Wih[i] = __float2half_rn(w_ih[i]);
        } else if (i < 16777216) {
            size_t j = i - 8388608; g_Whh[j] = __float2half_rn(w_hh[j]);
        } else if (i < 17825792) {
            size_t j = i - 16777216; g_Win[j] = __float2half_rn(w_in[j]);
        } else {
            size_t j = i - 17825792; g_Wo[j] = __float2half_rn(w_out[j]);
        }
    }
}

__global__ void gather_xe(const int* __restrict__ inp, const float* __restrict__ emb) {
    size_t i = (size_t)blockIdx.x * 256 + threadIdx.x;
    if (i < 4194304) {
        size_t tb = i >> 10, k = i & 1023;
        float v = emb[(size_t)inp[tb] * 1024 + k];
        split2(v, g_XEh[i], g_XEl[i]);
    }
}

__global__ void init_sk(const float* __restrict__ h0, const float* __restrict__ c0) {
    int i = blockIdx.x * 256 + threadIdx.x;
    if (i < BH) {
        float a = h0[i], b = h0[BH + i];
        g_h0F[1][i] = a; g_h0H[1][i] = __float2half_rn(a);   // h0(-1): slot 1
        g_h1F[3][i] = b; g_h1H[3][i] = __float2half_rn(b);   // h1(-1): slot 3
        g_c0F[i] = c0[i];
        g_c1F[i] = c0[BH + i];
    }
}

__global__ void final_k(float* __restrict__ hf, float* __restrict__ cf,
                        float* __restrict__ at) {
    int i = blockIdx.x * 256 + threadIdx.x;
    if (i < BH) {
        hf[i] = g_h0F[1][i];            // h0(63): 63&1 = 1
        hf[BH + i] = g_h1F[3][i];       // h1(63): 63&3 = 3
        cf[i] = g_c0F[i];
        cf[BH + i] = g_c1F[i];
    }
    if (i < BB * SS) at[i] = g_attn[i];
}

// ------------------------------- launch --------------------------------
extern "C" void kernel_launch(void* const* d_in, const int* in_sizes, int n_in,
                              void* d_out, int out_size) {
    (void)in_sizes; (void)n_in; (void)out_size;
    const int*   inp   = (const int*)d_in[0];
    const float* h0    = (const float*)d_in[1];
    const float* c0    = (const float*)d_in[2];
    const float* ctx   = (const float*)d_in[3];
    const float* emb   = (const float*)d_in[4];
    const float* w_ih  = (const float*)d_in[5];
    const float* w_hh  = (const float*)d_in[6];
    const float* b_ih  = (const float*)d_in[7];
    const float* b_hh  = (const float*)d_in[8];
    const float* w_in  = (const float*)d_in[9];
    const float* w_out = (const float*)d_in[10];

    float* out  = (float*)d_out;
    float* outs = out;
    float* hf   = out + (size_t)TT * BH;
    float* cf   = hf + 2 * BH;
    float* at   = cf + 2 * BH;

    cudaFuncSetAttribute(step_k, cudaFuncAttributeMaxDynamicSharedMemorySize, SMB_STEP);
    cudaFuncSetAttribute(x0_k,   cudaFuncAttributeMaxDynamicSharedMemorySize, SMB_X0);

    h16 *Wih, *Whh, *Win, *Wo, *XEh, *XEl;
    h16 *h0H, *h1H, *wcH;
    float *h0F, *h1F, *c0F, *c1F, *qF, *X0, *AT;
    cudaGetSymbolAddress((void**)&Wih, g_Wih); cudaGetSymbolAddress((void**)&Whh, g_Whh);
    cudaGetSymbolAddress((void**)&Win, g_Win); cudaGetSymbolAddress((void**)&Wo,  g_Wo);
    cudaGetSymbolAddress((void**)&XEh, g_XEh); cudaGetSymbolAddress((void**)&XEl, g_XEl);
    cudaGetSymbolAddress((void**)&h0F, g_h0F); cudaGetSymbolAddress((void**)&h1F, g_h1F);
    cudaGetSymbolAddress((void**)&h0H, g_h0H); cudaGetSymbolAddress((void**)&h1H, g_h1H);
    cudaGetSymbolAddress((void**)&c0F, g_c0F); cudaGetSymbolAddress((void**)&c1F, g_c1F);
    cudaGetSymbolAddress((void**)&qF,  g_qF);
    cudaGetSymbolAddress((void**)&wcH, g_wcH);
    cudaGetSymbolAddress((void**)&X0,  g_X0);
    cudaGetSymbolAddress((void**)&AT,  g_attn);

    split_w<<<16384, 256>>>(w_ih, w_hh, w_in, w_out);
    gather_xe<<<16384, 256>>>(inp, emb);
    init_sk<<<256, 256>>>(h0, c0);

    {   // X0 = XEh@W + XEl@W + biases, merged 128n tiles, grid (32, 64)
        StepP p = {};
        Seg& s = p.l0;
        s.A1 = XEh; s.A2 = XEl;
        s.W1 = Wih; s.wld = 1024; s.K = 1024;
        s.bias1 = b_ih; s.bias2 = b_hh;
        s.outC = X0; s.ldC = 4096; s.doTanh = 0;
        x0_k<<<dim3(32, 64), 512, SMB_X0>>>(p);
    }

    // Pipeline: launch k carries L1(k-1), OUT(k-4), L0(k), Q(k-2), ATTN(k-3).
    for (int k = 0; k <= 67; ++k) {
        StepP p = {};
        int tL1 = k - 1, tL0 = k, tQ = k - 2, tAt = k - 3, tOut = k - 4;
        if (tL1 >= 0 && tL1 < TT) {
            p.nL1 = 64;
            Seg& s = p.l1;
            s.A1 = h0H + (size_t)(tL1 & 1) * BH;
            s.A2 = h1H + (size_t)((tL1 - 1) & 3) * BH;
            s.W1 = Wih + 4194304;
            s.W2 = Whh + 4194304;
            s.wld = 1024; s.K = 2048;
            s.bias1 = b_ih + 4096; s.bias2 = b_hh + 4096;
            s.cSt = c1F;
            s.hF = h1F + (size_t)(tL1 & 3) * BH;
            s.hH = h1H + (size_t)(tL1 & 3) * BH;
        }
        if (tOut >= 0 && tOut < TT) {
            p.nOut = 16;
            Seg& s = p.o;
            s.A1 = wcH + (size_t)(tOut & 1) * BH;
            s.A2 = h1H + (size_t)(tOut & 3) * BH;
            s.W1 = Wo;
            s.W2 = Wo + 1024;
            s.wld = 2048; s.K = 2048;
            s.outC = outs + (size_t)tOut * BH; s.ldC = HH; s.doTanh = 1;
        }
        if (tL0 >= 0 && tL0 < TT) {
            p.nL0 = 64;
            Seg& s = p.l0;
            s.A1 = h0H + (size_t)((tL0 + 1) & 1) * BH;
            s.W1 = Whh; s.wld = 1024; s.K = 1024;
            s.addC = X0 + (size_t)tL0 * 64 * 4096;
            s.cSt = c0F;
            s.hF = h0F + (size_t)(tL0 & 1) * BH;
            s.hH = h0H + (size_t)(tL0 & 1) * BH;
        }
        if (tQ >= 0 && tQ < TT) {
            p.nQ = 16;
            Seg& s = p.q;
            s.A1 = h1H + (size_t)(tQ & 3) * BH;
            s.W1 = Win; s.wld = 1024; s.K = 1024;
            s.outC = qF + (size_t)(tQ & 1) * BH; s.ldC = HH; s.doTanh = 0;
        }
        if (tAt >= 0 && tAt < TT) {
            p.nAt = 64;
            p.atQ = qF + (size_t)(tAt & 1) * BH;
            p.atCtx = ctx;
            p.atWc = wcH + (size_t)(tAt & 1) * BH;
            p.atP = AT;
        }
        int grid = p.nL1 + p.nOut + p.nL0 + p.nQ + p.nAt;
        if (grid > 0) step_k<<<grid, 512, SMB_STEP>>>(p);
    }

    final_k<<<512, 256>>>(hf, cf, at);
}

// round 16
// speedup vs baseline: 1.4180x; 1.1394x over previous
#include <cuda_runtime.h>
#include <cuda_fp16.h>
#include <cstdint>

// Decoder: 2-layer LSTM + Luong attention. T=B=S=64, H=E=1024, L=2.
// Step GEMMs: mma.sync fp16, 64x64 tiles, 4 warpgroups w/ 4-way K-split,
// k16 chunks staged via cp.async.bulk (TMA 1D) from pre-packed padded blobs.
// X0 precompute: merged 64x128 cp.async tile (R15-proven).

#define TT 64
#define BB 64
#define SS 64
#define HH 1024
#define BH (BB * HH)

typedef unsigned long long ull;
typedef __half h16;

__device__ __forceinline__ float sigm_(float x) { return 1.f / (1.f + expf(-x)); }
__device__ __forceinline__ void split2(float v, h16& hi, h16& lo) {
    hi = __float2half_rn(v);
    lo = __float2half_rn(v - __half2float(hi));
}

// ------------------------------- scratch -------------------------------
// W blobs: [nblk][chunk][64 rows x 48B (32B data + 16B pad)] = 1536 h16/chunk
__device__ __align__(256) h16 g_WL1B[12582912];    // 64 nblk x 128 ch
__device__ __align__(256) h16 g_WL0B[6291456];     // 64 x 64
__device__ __align__(256) h16 g_WQB[1572864];      // 16 x 64
__device__ __align__(256) h16 g_WOB[3145728];      // 16 x 128
__device__ __align__(256) h16 g_Wih[4194304];      // w_ih layer0 (x0 only)
__device__ __align__(256) h16 g_XEh[4194304], g_XEl[4194304];
__device__ float g_X0[(size_t)4096 * 4096];
__device__ float g_h0F[2][BH], g_h1F[4][BH], g_c0F[BH], g_c1F[BH];
// A blobs: [64 chunks][64 b x 48B] = 98304 h16 per slot
__device__ __align__(256) h16 g_h0B[2][98304];
__device__ __align__(256) h16 g_h1B[4][98304];
__device__ __align__(256) h16 g_wcB[2][98304];
__device__ float g_qF[2][BH];
__device__ float g_attn[BB * SS];

// ----------------------------- ptx helpers -----------------------------
__device__ __forceinline__ uint32_t s2u(const void* p) {
    uint32_t a;
    asm("{ .reg .u64 t; cvta.to.shared.u64 t, %1; cvt.u32.u64 %0, t; }"
        : "=r"(a) : "l"(p));
    return a;
}
__device__ __forceinline__ void cpa16(uint32_t dst, const void* src) {
    asm volatile("cp.async.cg.shared.global [%0], [%1], 16;"
                 :: "r"(dst), "l"(src) : "memory");
}
__device__ __forceinline__ void bulkcp(uint32_t dst, const void* src, uint32_t mb) {
    asm volatile(
        "cp.async.bulk.shared::cluster.global.mbarrier::complete_tx::bytes "
        "[%0], [%1], %2, [%3];"
        :: "r"(dst), "l"(src), "r"(3072u), "r"(mb) : "memory");
}
__device__ __forceinline__ void mbar_init(uint32_t a, uint32_t cnt) {
    asm volatile("mbarrier.init.shared.b64 [%0], %1;" :: "r"(a), "r"(cnt) : "memory");
}
__device__ __forceinline__ void expect_tx(uint32_t mb, uint32_t bytes) {
    asm volatile("mbarrier.arrive.expect_tx.shared.b64 _, [%0], %1;"
                 :: "r"(mb), "r"(bytes) : "memory");
}
__device__ __forceinline__ void mbar_wait(uint32_t a, uint32_t parity) {
    asm volatile(
        "{\n\t.reg .pred P;\n\t"
        "W_%=:\n\t"
        "mbarrier.try_wait.parity.shared.b64 P, [%0], %1, 0x989680;\n\t"
        "@!P bra W_%=;\n\t}"
        :: "r"(a), "r"(parity) : "memory");
}
__device__ __forceinline__ void ldsm4(uint32_t* r, uint32_t addr) {
    asm volatile("ldmatrix.sync.aligned.m8n8.x4.shared.b16 {%0,%1,%2,%3}, [%4];"
                 : "=r"(r[0]), "=r"(r[1]), "=r"(r[2]), "=r"(r[3]) : "r"(addr));
}
__device__ __forceinline__ void mma16816(float* d, const uint32_t* a, const uint32_t* b) {
    asm volatile(
        "mma.sync.aligned.m16n8k16.row.col.f32.f16.f16.f32 "
        "{%0,%1,%2,%3},{%4,%5,%6,%7},{%8,%9},{%0,%1,%2,%3};"
        : "+f"(d[0]), "+f"(d[1]), "+f"(d[2]), "+f"(d[3])
        : "r"(a[0]), "r"(a[1]), "r"(a[2]), "r"(a[3]), "r"(b[0]), "r"(b[1]));
}
__device__ __forceinline__ void barw(int wg) {
    asm volatile("bar.sync %0, 128;" :: "r"(wg + 1) : "memory");
}

// ---------------------------- GEMM segment -----------------------------
// C[64 m(batch), 64 n] = A @ W^T. 512 threads = 4 wgs of 128; each wg does
// NC/4 chunks into a partial accumulator; combined in epilogue.
// A and W are chunk-blob format (1536 h16 per k16 chunk, 48B padded rows).
// PAIR2: NC=128, A chunks <64 from A1, >=64 from A2.
struct Seg {
    const h16 *A1, *A2;
    const h16 *WB;            // [nblk][NC][1536]
    int NC;
    const float *addC, *bias1, *bias2;
    float *cSt, *hF;
    h16 *hB;                  // A-blob output (cell epilogue)
    float *outC; int ldC, doTanh;
};

// smem: 4 wg x 4 stages x (A 3072 | W 3072) = 98304 B; mbars at 98304+.
#define SMB_STEP (98304 + 128)
#define SMB_X0   (4 * 4 * 12288)

template <bool PAIR2, int EPI>
__device__ void mgemm(const Seg& a, char* sm, int nblk) {
    const int tx = threadIdx.x;
    const int wg = tx >> 7;
    const int wtx = tx & 127;
    const int warp = wtx >> 5, lane = tx & 31;
    const int wm = warp << 4;
    const uint32_t smb = s2u(sm);
    const uint32_t wgB = smb + wg * 24576;
    const uint32_t mbB = smb + 98304 + wg * 32;

    const int ncPer = a.NC >> 2;
    const int cbase = wg * ncPer;

    if (wtx == 0)
        for (int s = 0; s < 4; ++s) mbar_init(mbB + s * 8, 1);
    __syncthreads();

#define PRODUCE(cl)                                                            \
    {                                                                          \
        int gc = cbase + (cl);                                                 \
        int s = (cl) & 3;                                                      \
        uint32_t mb = mbB + s * 8;                                             \
        uint32_t dst = wgB + s * 6144;                                         \
        expect_tx(mb, 6144);                                                   \
        const h16* asrc = (PAIR2 && gc >= 64) ? a.A2 + (size_t)(gc - 64) * 1536\
                                              : a.A1 + (size_t)gc * 1536;      \
        bulkcp(dst, asrc, mb);                                                 \
        bulkcp(dst + 3072, a.WB + ((size_t)nblk * a.NC + gc) * 1536, mb);      \
    }

    if (wtx == 0) {
        int np = ncPer < 4 ? ncPer : 4;
        for (int cl = 0; cl < np; ++cl) PRODUCE(cl)
    }

    float acc[8][4] = {};
    const uint32_t aoff = (uint32_t)((wm + (lane & 15)) * 48 + ((lane >> 4) << 4));
    const uint32_t boff = (uint32_t)(3072 + ((((lane >> 4) << 3) + (lane & 7))) * 48
                                     + (((lane >> 3) & 1) << 4));

    for (int c = 0; c < ncPer; ++c) {
        int s = c & 3;
        mbar_wait(mbB + s * 8, (c >> 2) & 1);
        const uint32_t base = wgB + s * 6144;
        uint32_t ah[4], bw[16];
        ldsm4(ah, base + aoff);
#pragma unroll
        for (int j = 0; j < 4; ++j)
            ldsm4(bw + 4 * j, base + boff + j * 16 * 48);
#pragma unroll
        for (int nt = 0; nt < 8; ++nt)
            mma16816(acc[nt], ah, bw + 2 * nt);
        barw(wg);
        if (wtx == 0 && c + 4 < ncPer) PRODUCE(c + 4)
    }
#undef PRODUCE
    __syncthreads();

    float* St = (float*)sm;
    float* Sw = St + wg * 4224;          // 64*66
    const int rr = wm + (lane >> 2);
#pragma unroll
    for (int nt = 0; nt < 8; ++nt) {
        int cc = nt * 8 + ((lane & 3) << 1);
        Sw[cc * 66 + rr]           = acc[nt][0];
        Sw[(cc + 1) * 66 + rr]     = acc[nt][1];
        Sw[cc * 66 + rr + 8]       = acc[nt][2];
        Sw[(cc + 1) * 66 + rr + 8] = acc[nt][3];
    }
    __syncthreads();

    if (EPI == 0) {      // fused LSTM cell (cols = gate*16 + jj)
#pragma unroll
        for (int it = 0; it < 2; ++it) {
            int idx = tx + it * 512;
            int b = idx & 63, jj = idx >> 6;
            int jg = nblk * 16 + jj;
            float gi = St[jj * 66 + b]        + St[4224 + jj * 66 + b]
                     + St[8448 + jj * 66 + b] + St[12672 + jj * 66 + b];
            float gf = St[(16 + jj) * 66 + b]        + St[4224 + (16 + jj) * 66 + b]
                     + St[8448 + (16 + jj) * 66 + b] + St[12672 + (16 + jj) * 66 + b];
            float gg = St[(32 + jj) * 66 + b]        + St[4224 + (32 + jj) * 66 + b]
                     + St[8448 + (32 + jj) * 66 + b] + St[12672 + (32 + jj) * 66 + b];
            float go = St[(48 + jj) * 66 + b]        + St[4224 + (48 + jj) * 66 + b]
                     + St[8448 + (48 + jj) * 66 + b] + St[12672 + (48 + jj) * 66 + b];
            if (a.addC) {
                const float* ac = a.addC + (size_t)b * 4096 + jg;
                gi += ac[0]; gf += ac[1024]; gg += ac[2048]; go += ac[3072];
            }
            if (a.bias1) {
                gi += a.bias1[jg] + a.bias2[jg];
                gf += a.bias1[1024 + jg] + a.bias2[1024 + jg];
                gg += a.bias1[2048 + jg] + a.bias2[2048 + jg];
                go += a.bias1[3072 + jg] + a.bias2[3072 + jg];
            }
            float cc2 = sigm_(gf) * a.cSt[b * HH + jg] + sigm_(gi) * tanhf(gg);
            a.cSt[b * HH + jg] = cc2;
            float h = sigm_(go) * tanhf(cc2);
            a.hF[b * HH + jg] = h;
            a.hB[(jg >> 4) * 1536 + b * 24 + (jg & 15)] = __float2half_rn(h);
        }
    } else {             // plain store (optional bias / tanh)
#pragma unroll
        for (int it = 0; it < 8; ++it) {
            int idx = tx + it * 512;
            int row = idx >> 6, col = idx & 63;
            float v = St[col * 66 + row]        + St[4224 + col * 66 + row]
                    + St[8448 + col * 66 + row] + St[12672 + col * 66 + row];
            int cg = nblk * 64 + col;
            if (a.bias1) v += a.bias1[cg] + a.bias2[cg];
            if (a.doTanh) v = tanhf(v);
            a.outC[(size_t)row * a.ldC + cg] = v;
        }
    }
}

// -------------- X0 merged GEMM (cp.async path, R15-proven) --------------
struct XSeg {
    const h16 *A1, *A2, *W1;
    const float *bias1, *bias2;
    float* outC;
};

__device__ void xgemm(const XSeg& a, char* sm, int mblk, int nblk) {
    const int STG = 12288;
    const int tx = threadIdx.x;
    const int wg = tx >> 7;
    const int wtx = tx & 127;
    const int warp = wtx >> 5, lane = tx & 31;
    const int wm = warp << 4;
    const uint32_t smb = s2u(sm) + wg * (4 * STG);

    const int sr = wtx >> 1, su = wtx & 1;
    const int am = mblk * 64 + sr;
    const int wrA = nblk * 128 + sr;
    const int wrB = nblk * 128 + sr + 64;

    const h16 *a1 = a.A1, *a2 = a.A2, *w1 = a.W1;
    const int Kwg = 256, kbase = wg * Kwg;
    const size_t arow = (size_t)am * 1024;
    const size_t wroA = (size_t)wrA * 1024;
    const size_t wroB = (size_t)wrB * 1024;

    float acc[16][4] = {};
    const int nc = Kwg >> 4;

    const uint32_t aoff = (uint32_t)((wm + (lane & 15)) * 48 + ((lane >> 4) << 4));
    const uint32_t boff = (uint32_t)(((((lane >> 4) << 3) + (lane & 7))) * 48
                                     + (((lane >> 3) & 1) << 4));

#define XSTAGE(c)                                                              \
    {                                                                          \
        int kl = kbase + ((c) << 4);                                           \
        uint32_t db = smb + ((c) & 3) * STG;                                   \
        uint32_t ro = sr * 48 + (su << 4);                                     \
        cpa16(db + ro, a1 + arow + kl + su * 8);                               \
        cpa16(db + 3072 + ro, a2 + arow + kl + su * 8);                        \
        cpa16(db + 6144 + ro, w1 + wroA + kl + su * 8);                        \
        cpa16(db + 6144 + ro + 64 * 48, w1 + wroB + kl + su * 8);              \
        asm volatile("cp.async.commit_group;" ::: "memory");                   \
    }

    XSTAGE(0) XSTAGE(1) XSTAGE(2)
    for (int c = 0; c < nc; ++c) {
        if (c + 3 < nc) {
            asm volatile("cp.async.wait_group 2;" ::: "memory");
            barw(wg);
            XSTAGE(c + 3)
        } else {
            asm volatile("cp.async.wait_group 0;" ::: "memory");
            barw(wg);
        }
        const uint32_t base = smb + (c & 3) * STG;
        uint32_t ah[4], al[4], bw[32];
        ldsm4(ah, base + aoff);
        ldsm4(al, base + 3072 + aoff);
#pragma unroll
        for (int j = 0; j < 8; ++j)
            ldsm4(bw + 4 * j, base + 6144 + boff + j * 16 * 48);
#pragma unroll
        for (int nt = 0; nt < 16; ++nt) {
            mma16816(acc[nt], ah, bw + 2 * nt);
            mma16816(acc[nt], al, bw + 2 * nt);
        }
    }
#undef XSTAGE
    __syncthreads();

    float* St = (float*)sm;
    float* Sw = St + wg * 8448;
    const int rr = wm + (lane >> 2);
#pragma unroll
    for (int nt = 0; nt < 16; ++nt) {
        int cc = nt * 8 + ((lane & 3) << 1);
        Sw[cc * 66 + rr]           = acc[nt][0];
        Sw[(cc + 1) * 66 + rr]     = acc[nt][1];
        Sw[cc * 66 + rr + 8]       = acc[nt][2];
        Sw[(cc + 1) * 66 + rr + 8] = acc[nt][3];
    }
    __syncthreads();

#pragma unroll
    for (int it = 0; it < 16; ++it) {
        int idx = tx + it * 512;
        int row = idx >> 7, col = idx & 127;
        float v = St[col * 66 + row]         + St[8448 + col * 66 + row]
                + St[16896 + col * 66 + row] + St[25344 + col * 66 + row];
        int cg = nblk * 128 + col;
        v += a.bias1[cg] + a.bias2[cg];
        a.outC[(size_t)(mblk * 64 + row) * 4096 + cg] = v;
    }
}

// ------------------------------ step kernel ----------------------------
// Block order [ATTN, OUT, L1, L0, Q] (R11/R15-proven placement).
struct StepP {
    int nL1, nOut, nL0, nQ, nAt;
    Seg l1, o, l0, q;
    const float *atQ, *atCtx;
    h16 *atWc;
    float* atP;
};

__global__ __launch_bounds__(512, 1) void step_k(StepP p) {
    extern __shared__ __align__(16) char sm[];
    const int bid = blockIdx.x;
    const int r0 = p.nAt, r1 = r0 + p.nOut, r2 = r1 + p.nL1, r3 = r2 + p.nL0;

    if (bid >= r0 && bid < r1) {
        mgemm<true, 1>(p.o, sm, bid - r0);
    } else if (bid >= r1 && bid < r2) {
        mgemm<true, 0>(p.l1, sm, bid - r1);
    } else if (bid >= r2 && bid < r3) {
        mgemm<false, 0>(p.l0, sm, bid - r2);
    } else if (bid >= r3) {
        mgemm<false, 1>(p.q, sm, bid - r3);
    } else {                              // ATTN: one block per batch b
        int b = bid;
        float* qs = (float*)sm;           // 1024 floats
        float* sc = qs + 1024;            // 64 floats
        const int tx = threadIdx.x;
        *(float2*)&qs[tx * 2] = *(const float2*)&p.atQ[(size_t)b * HH + tx * 2];
        __syncthreads();
        const int wid = tx >> 5, lane = tx & 31;
        for (int s = wid; s < SS; s += 16) {
            const float* cp = p.atCtx + ((size_t)s * BB + b) * HH;
            float acc = 0.f;
#pragma unroll
            for (int i = 0; i < 8; ++i) {
                float4 c4 = *(const float4*)(cp + i * 128 + lane * 4);
                float4 q4 = *(const float4*)&qs[i * 128 + lane * 4];
                acc += c4.x * q4.x + c4.y * q4.y + c4.z * q4.z + c4.w * q4.w;
            }
#pragma unroll
            for (int o = 16; o; o >>= 1) acc += __shfl_down_sync(0xFFFFFFFFu, acc, o);
            if (lane == 0) sc[s] = acc;
        }
        __syncthreads();
        if (tx == 0) {
            float mx = sc[0];
            for (int s = 1; s < SS; ++s) mx = fmaxf(mx, sc[s]);
            float sum = 0.f;
            for (int s = 0; s < SS; ++s) { float e = expf(sc[s] - mx); sc[s] = e; sum += e; }
            float inv = 1.f / sum;
            for (int s = 0; s < SS; ++s) sc[s] *= inv;
        }
        __syncthreads();
        if (tx < SS) p.atP[b * SS + tx] = sc[tx];
        for (int k = tx; k < HH; k += 512) {
            float acc = 0.f;
#pragma unroll 8
            for (int s = 0; s < SS; ++s)
                acc += sc[s] * p.atCtx[((size_t)s * BB + b) * HH + k];
            p.atWc[(k >> 4) * 1536 + b * 24 + (k & 15)] = __float2half_rn(acc);
        }
    }
}

__global__ __launch_bounds__(512, 1) void x0_k(XSeg p) {
    extern __shared__ __align__(16) char sm[];
    xgemm(p, sm, blockIdx.y, blockIdx.x);
}

// ----------------------------- init kernels ----------------------------
// Pack W blobs (padded 48B-row layout, gate remap baked in) + w_ih0 fp16.
__global__ void pack_w(const float* __restrict__ w_ih, const float* __restrict__ w_hh,
                       const float* __restrict__ w_in, const float* __restrict__ w_out) {
    const size_t N1 = 8388608, N0 = 4194304, NQ = 1048576, NO = 2097152;
    const size_t N = N1 + N0 + NQ + NO + 4194304;
    for (size_t i = (size_t)blockIdx.x * 256 + threadIdx.x; i < N;
         i += (size_t)gridDim.x * 256) {
        if (i < N1) {                        // WL1: [64][128 ch] Wih1|Whh1
            size_t j = i;
            int nblk = j >> 17; j &= 131071;
            int c = j >> 10; j &= 1023;
            int row = j >> 4, kk = j & 15;
            int wr = (row >> 4) * 1024 + nblk * 16 + (row & 15);
            float v = (c < 64) ? w_ih[4194304 + (size_t)wr * 1024 + c * 16 + kk]
                               : w_hh[4194304 + (size_t)wr * 1024 + (c - 64) * 16 + kk];
            g_WL1B[((size_t)nblk * 128 + c) * 1536 + row * 24 + kk] = __float2half_rn(v);
        } else if (i < N1 + N0) {            // WL0: [64][64 ch] Whh0
            size_t j = i - N1;
            int nblk = j >> 16; j &= 65535;
            int c = j >> 10; j &= 1023;
            int row = j >> 4, kk = j & 15;
            int wr = (row >> 4) * 1024 + nblk * 16 + (row & 15);
            float v = w_hh[(size_t)wr * 1024 + c * 16 + kk];
            g_WL0B[((size_t)nblk * 64 + c) * 1536 + row * 24 + kk] = __float2half_rn(v);
        } else if (i < N1 + N0 + NQ) {       // WQ: [16][64 ch] Win
            size_t j = i - N1 - N0;
            int nblk = j >> 16; j &= 65535;
            int c = j >> 10; j &= 1023;
            int row = j >> 4, kk = j & 15;
            int wr = nblk * 64 + row;
            float v = w_in[(size_t)wr * 1024 + c * 16 + kk];
            g_WQB[((size_t)nblk * 64 + c) * 1536 + row * 24 + kk] = __float2half_rn(v);
        } else if (i < N1 + N0 + NQ + NO) {  // WO: [16][128 ch] Wo cols split
            size_t j = i - N1 - N0 - NQ;
            int nblk = j >> 17; j &= 131071;
            int c = j >> 10; j &= 1023;
            int row = j >> 4, kk = j & 15;
            int wr = nblk * 64 + row;
            float v = (c < 64) ? w_out[(size_t)wr * 2048 + c * 16 + kk]
                               : w_out[(size_t)wr * 2048 + 1024 + (c - 64) * 16 + kk];
            g_WOB[((size_t)nblk * 128 + c) * 1536 + row * 24 + kk] = __float2half_rn(v);
        } else {                             // w_ih layer0 fp16 (x0)
            size_t j = i - N1 - N0 - NQ - NO;
            g_Wih[j] = __float2half_rn(w_ih[j]);
        }
    }
}

__global__ void gather_xe(const int* __restrict__ inp, const float* __restrict__ emb) {
    size_t i = (size_t)blockIdx.x * 256 + threadIdx.x;
    if (i < 4194304) {
        size_t tb = i >> 10, k = i & 1023;
        float v = emb[(size_t)inp[tb] * 1024 + k];
        split2(v, g_XEh[i], g_XEl[i]);
    }
}

__global__ void init_sk(const float* __restrict__ h0, const float* __restrict__ c0) {
    int i = blockIdx.x * 256 + threadIdx.x;
    if (i < BH) {
        int b = i >> 10, j = i & 1023;
        int off = (j >> 4) * 1536 + b * 24 + (j & 15);
        float a = h0[i], bb = h0[BH + i];
        g_h0F[1][i] = a; g_h0B[1][off] = __float2half_rn(a);   // h0(-1): slot 1
        g_h1F[3][i] = bb; g_h1B[3][off] = __float2half_rn(bb); // h1(-1): slot 3
        g_c0F[i] = c0[i];
        g_c1F[i] = c0[BH + i];
    }
}

__global__ void final_k(float* __restrict__ hf, float* __restrict__ cf,
                        float* __restrict__ at) {
    int i = blockIdx.x * 256 + threadIdx.x;
    if (i < BH) {
        hf[i] = g_h0F[1][i];            // h0(63): 63&1 = 1
        hf[BH + i] = g_h1F[3][i];       // h1(63): 63&3 = 3
        cf[i] = g_c0F[i];
        cf[BH + i] = g_c1F[i];
    }
    if (i < BB * SS) at[i] = g_attn[i];
}

// ------------------------------- launch --------------------------------
extern "C" void kernel_launch(void* const* d_in, const int* in_sizes, int n_in,
                              void* d_out, int out_size) {
    (void)in_sizes; (void)n_in; (void)out_size;
    const int*   inp   = (const int*)d_in[0];
    const float* h0    = (const float*)d_in[1];
    const float* c0    = (const float*)d_in[2];
    const float* ctx   = (const float*)d_in[3];
    const float* emb   = (const float*)d_in[4];
    const float* w_ih  = (const float*)d_in[5];
    const float* w_hh  = (const float*)d_in[6];
    const float* b_ih  = (const float*)d_in[7];
    const float* b_hh  = (const float*)d_in[8];
    const float* w_in  = (const float*)d_in[9];
    const float* w_out = (const float*)d_in[10];

    float* out  = (float*)d_out;
    float* outs = out;
    float* hf   = out + (size_t)TT * BH;
    float* cf   = hf + 2 * BH;
    float* at   = cf + 2 * BH;

    cudaFuncSetAttribute(step_k, cudaFuncAttributeMaxDynamicSharedMemorySize, SMB_STEP);
    cudaFuncSetAttribute(x0_k,   cudaFuncAttributeMaxDynamicSharedMemorySize, SMB_X0);

    h16 *WL1B, *WL0B, *WQB, *WOB, *Wih, *XEh, *XEl;
    h16 *h0B, *h1B, *wcB;
    float *h0F, *h1F, *c0F, *c1F, *qF, *X0, *AT;
    cudaGetSymbolAddress((void**)&WL1B, g_WL1B); cudaGetSymbolAddress((void**)&WL0B, g_WL0B);
    cudaGetSymbolAddress((void**)&WQB,  g_WQB);  cudaGetSymbolAddress((void**)&WOB,  g_WOB);
    cudaGetSymbolAddress((void**)&Wih,  g_Wih);
    cudaGetSymbolAddress((void**)&XEh,  g_XEh);  cudaGetSymbolAddress((void**)&XEl,  g_XEl);
    cudaGetSymbolAddress((void**)&h0F, g_h0F); cudaGetSymbolAddress((void**)&h1F, g_h1F);
    cudaGetSymbolAddress((void**)&h0B, g_h0B); cudaGetSymbolAddress((void**)&h1B, g_h1B);
    cudaGetSymbolAddress((void**)&c0F, g_c0F); cudaGetSymbolAddress((void**)&c1F, g_c1F);
    cudaGetSymbolAddress((void**)&qF,  g_qF);
    cudaGetSymbolAddress((void**)&wcB, g_wcB);
    cudaGetSymbolAddress((void**)&X0,  g_X0);
    cudaGetSymbolAddress((void**)&AT,  g_attn);

    pack_w<<<16384, 256>>>(w_ih, w_hh, w_in, w_out);
    gather_xe<<<16384, 256>>>(inp, emb);
    init_sk<<<256, 256>>>(h0, c0);

    {   // X0 = XEh@W + XEl@W + biases, merged 128n tiles, grid (32, 64)
        XSeg p;
        p.A1 = XEh; p.A2 = XEl; p.W1 = Wih;
        p.bias1 = b_ih; p.bias2 = b_hh;
        p.outC = X0;
        x0_k<<<dim3(32, 64), 512, SMB_X0>>>(p);
    }

    // Pipeline: launch k carries L1(k-1), OUT(k-4), L0(k), Q(k-2), ATTN(k-3).
    for (int k = 0; k <= 67; ++k) {
        StepP p = {};
        int tL1 = k - 1, tL0 = k, tQ = k - 2, tAt = k - 3, tOut = k - 4;
        if (tL1 >= 0 && tL1 < TT) {
            p.nL1 = 64;
            Seg& s = p.l1;
            s.A1 = h0B + (size_t)(tL1 & 1) * 98304;
            s.A2 = h1B + (size_t)((tL1 - 1) & 3) * 98304;
            s.WB = WL1B; s.NC = 128;
            s.bias1 = b_ih + 4096; s.bias2 = b_hh + 4096;
            s.cSt = c1F;
            s.hF = h1F + (size_t)(tL1 & 3) * BH;
            s.hB = h1B + (size_t)(tL1 & 3) * 98304;
        }
        if (tOut >= 0 && tOut < TT) {
            p.nOut = 16;
            Seg& s = p.o;
            s.A1 = wcB + (size_t)(tOut & 1) * 98304;
            s.A2 = h1B + (size_t)(tOut & 3) * 98304;
            s.WB = WOB; s.NC = 128;
            s.outC = outs + (size_t)tOut * BH; s.ldC = HH; s.doTanh = 1;
        }
        if (tL0 >= 0 && tL0 < TT) {
            p.nL0 = 64;
            Seg& s = p.l0;
            s.A1 = h0B + (size_t)((tL0 + 1) & 1) * 98304;
            s.WB = WL0B; s.NC = 64;
            s.addC = X0 + (size_t)tL0 * 64 * 4096;
            s.cSt = c0F;
            s.hF = h0F + (size_t)(tL0 & 1) * BH;
            s.hB = h0B + (size_t)(tL0 & 1) * 98304;
        }
        if (tQ >= 0 && tQ < TT) {
            p.nQ = 16;
            Seg& s = p.q;
            s.A1 = h1B + (size_t)(tQ & 3) * 98304;
            s.WB = WQB; s.NC = 64;
            s.outC = qF + (size_t)(tQ & 1) * BH; s.ldC = HH; s.doTanh = 0;
        }
        if (tAt >= 0 && tAt < TT) {
            p.nAt = 64;
            p.atQ = qF + (size_t)(tAt & 1) * BH;
            p.atCtx = ctx;
            p.atWc = wcB + (size_t)(tAt & 1) * 98304;
            p.atP = AT;
        }
        int grid = p.nL1 + p.nOut + p.nL0 + p.nQ + p.nAt;
        if (grid > 0) step_k<<<grid, 512, SMB_STEP>>>(p);
    }

    final_k<<<512, 256>>>(hf, cf, at);
}

// round 17
// speedup vs baseline: 1.4922x; 1.0523x over previous
#include <cuda_runtime.h>
#include <cuda_fp16.h>
#include <cstdint>

// Decoder: 2-layer LSTM + Luong attention. T=B=S=64, H=E=1024, L=2.
// All GEMMs: mma.sync fp16, staged via cp.async.bulk (TMA 1D) from
// pre-packed padded blobs. Step: 64x64 tiles, 4 wgs, 6-stage pipeline.
// X0: merged 64x128 tiles, 4-stage pipeline.

#define TT 64
#define BB 64
#define SS 64
#define HH 1024
#define BH (BB * HH)

typedef unsigned long long ull;
typedef __half h16;

__device__ __forceinline__ float sigm_(float x) { return 1.f / (1.f + expf(-x)); }

// ------------------------------- scratch -------------------------------
// W blobs: [nblk][chunk][rows x 48B (32B data + 16B pad)]
__device__ __align__(256) h16 g_WL1B[12582912];    // 64 nblk x 128 ch x 64 rows
__device__ __align__(256) h16 g_WL0B[6291456];     // 64 x 64 x 64
__device__ __align__(256) h16 g_WQB[1572864];      // 16 x 64 x 64
__device__ __align__(256) h16 g_WOB[3145728];      // 16 x 128 x 64
__device__ __align__(256) h16 g_WXB[6291456];      // 32 nblk x 64 ch x 128 rows
__device__ __align__(256) h16 g_XEB[6291456];      // 64 mblk x 64 ch x 64 rows
__device__ float g_X0[(size_t)4096 * 4096];
__device__ float g_h0F[2][BH], g_h1F[4][BH], g_c0F[BH], g_c1F[BH];
// A blobs: [64 chunks][64 b x 48B] = 98304 h16 per slot
__device__ __align__(256) h16 g_h0B[2][98304];
__device__ __align__(256) h16 g_h1B[4][98304];
__device__ __align__(256) h16 g_wcB[2][98304];
__device__ float g_qF[2][BH];
__device__ float g_attn[BB * SS];

// ----------------------------- ptx helpers -----------------------------
__device__ __forceinline__ uint32_t s2u(const void* p) {
    uint32_t a;
    asm("{ .reg .u64 t; cvta.to.shared.u64 t, %1; cvt.u32.u64 %0, t; }"
        : "=r"(a) : "l"(p));
    return a;
}
__device__ __forceinline__ void bulkcp(uint32_t dst, const void* src,
                                       uint32_t bytes, uint32_t mb) {
    asm volatile(
        "cp.async.bulk.shared::cluster.global.mbarrier::complete_tx::bytes "
        "[%0], [%1], %2, [%3];"
        :: "r"(dst), "l"(src), "r"(bytes), "r"(mb) : "memory");
}
__device__ __forceinline__ void mbar_init(uint32_t a, uint32_t cnt) {
    asm volatile("mbarrier.init.shared.b64 [%0], %1;" :: "r"(a), "r"(cnt) : "memory");
}
__device__ __forceinline__ void expect_tx(uint32_t mb, uint32_t bytes) {
    asm volatile("mbarrier.arrive.expect_tx.shared.b64 _, [%0], %1;"
                 :: "r"(mb), "r"(bytes) : "memory");
}
__device__ __forceinline__ void mbar_wait(uint32_t a, uint32_t parity) {
    asm volatile(
        "{\n\t.reg .pred P;\n\t"
        "W_%=:\n\t"
        "mbarrier.try_wait.parity.shared.b64 P, [%0], %1, 0x989680;\n\t"
        "@!P bra W_%=;\n\t}"
        :: "r"(a), "r"(parity) : "memory");
}
__device__ __forceinline__ void ldsm4(uint32_t* r, uint32_t addr) {
    asm volatile("ldmatrix.sync.aligned.m8n8.x4.shared.b16 {%0,%1,%2,%3}, [%4];"
                 : "=r"(r[0]), "=r"(r[1]), "=r"(r[2]), "=r"(r[3]) : "r"(addr));
}
__device__ __forceinline__ void mma16816(float* d, const uint32_t* a, const uint32_t* b) {
    asm volatile(
        "mma.sync.aligned.m16n8k16.row.col.f32.f16.f16.f32 "
        "{%0,%1,%2,%3},{%4,%5,%6,%7},{%8,%9},{%0,%1,%2,%3};"
        : "+f"(d[0]), "+f"(d[1]), "+f"(d[2]), "+f"(d[3])
        : "r"(a[0]), "r"(a[1]), "r"(a[2]), "r"(a[3]), "r"(b[0]), "r"(b[1]));
}
__device__ __forceinline__ void barw(int wg) {
    asm volatile("bar.sync %0, 128;" :: "r"(wg + 1) : "memory");
}

// smem: step 4 wg x 6 stages x 6144 = 147456; xt 4 wg x 4 stages x 9216 =
// 147456. mbars live at 147456.. (step 6/wg, xt 4/wg).
#define SMB 147712

// ---------------------------- step GEMM --------------------------------
// C[64 m(batch), 64 n] = A @ W^T. 4 wgs, each NC/4 chunks; partials summed
// in epilogue. Blob format: 1536 h16 per k16 chunk (48B padded rows).
struct Seg {
    const h16 *A1, *A2;
    const h16 *WB;            // [nblk][NC][1536]
    int NC;
    const float *addC, *bias1, *bias2;
    float *cSt, *hF;
    h16 *hB;
    float *outC; int ldC, doTanh;
};

template <bool PAIR2, int EPI>
__device__ void mgemm(const Seg& a, char* sm, int nblk) {
    const int tx = threadIdx.x;
    const int wg = tx >> 7;
    const int wtx = tx & 127;
    const int warp = wtx >> 5, lane = tx & 31;
    const int wm = warp << 4;
    const uint32_t smb = s2u(sm);
    const uint32_t wgB = smb + wg * 36864;
    const uint32_t mbB = smb + 147456 + wg * 48;

    const int ncPer = a.NC >> 2;
    const int cbase = wg * ncPer;

    if (wtx == 0)
        for (int s = 0; s < 6; ++s) mbar_init(mbB + s * 8, 1);
    __syncthreads();

#define PRODUCE(cl)                                                            \
    {                                                                          \
        int gc = cbase + (cl);                                                 \
        int s = (cl) % 6;                                                      \
        uint32_t mb = mbB + s * 8;                                             \
        uint32_t dst = wgB + s * 6144;                                         \
        expect_tx(mb, 6144);                                                   \
        const h16* asrc = (PAIR2 && gc >= 64) ? a.A2 + (size_t)(gc - 64) * 1536\
                                              : a.A1 + (size_t)gc * 1536;      \
        bulkcp(dst, asrc, 3072, mb);                                           \
        bulkcp(dst + 3072, a.WB + ((size_t)nblk * a.NC + gc) * 1536, 3072, mb);\
    }

    if (wtx == 0)
        for (int cl = 0; cl < 6; ++cl) PRODUCE(cl)

    float acc[8][4] = {};
    const uint32_t aoff = (uint32_t)((wm + (lane & 15)) * 48 + ((lane >> 4) << 4));
    const uint32_t boff = (uint32_t)(3072 + ((((lane >> 4) << 3) + (lane & 7))) * 48
                                     + (((lane >> 3) & 1) << 4));

    for (int c = 0; c < ncPer; ++c) {
        int s = c % 6;
        mbar_wait(mbB + s * 8, (c / 6) & 1);
        const uint32_t base = wgB + s * 6144;
        uint32_t ah[4], bw[16];
        ldsm4(ah, base + aoff);
#pragma unroll
        for (int j = 0; j < 4; ++j)
            ldsm4(bw + 4 * j, base + boff + j * 16 * 48);
#pragma unroll
        for (int nt = 0; nt < 8; ++nt)
            mma16816(acc[nt], ah, bw + 2 * nt);
        barw(wg);
        if (wtx == 0 && c + 6 < ncPer) PRODUCE(c + 6)
    }
#undef PRODUCE
    __syncthreads();

    float* St = (float*)sm;
    float* Sw = St + wg * 4224;          // 64*66
    const int rr = wm + (lane >> 2);
#pragma unroll
    for (int nt = 0; nt < 8; ++nt) {
        int cc = nt * 8 + ((lane & 3) << 1);
        Sw[cc * 66 + rr]           = acc[nt][0];
        Sw[(cc + 1) * 66 + rr]     = acc[nt][1];
        Sw[cc * 66 + rr + 8]       = acc[nt][2];
        Sw[(cc + 1) * 66 + rr + 8] = acc[nt][3];
    }
    __syncthreads();

    if (EPI == 0) {      // fused LSTM cell (cols = gate*16 + jj)
#pragma unroll
        for (int it = 0; it < 2; ++it) {
            int idx = tx + it * 512;
            int b = idx & 63, jj = idx >> 6;
            int jg = nblk * 16 + jj;
            float gi = St[jj * 66 + b]        + St[4224 + jj * 66 + b]
                     + St[8448 + jj * 66 + b] + St[12672 + jj * 66 + b];
            float gf = St[(16 + jj) * 66 + b]        + St[4224 + (16 + jj) * 66 + b]
                     + St[8448 + (16 + jj) * 66 + b] + St[12672 + (16 + jj) * 66 + b];
            float gg = St[(32 + jj) * 66 + b]        + St[4224 + (32 + jj) * 66 + b]
                     + St[8448 + (32 + jj) * 66 + b] + St[12672 + (32 + jj) * 66 + b];
            float go = St[(48 + jj) * 66 + b]        + St[4224 + (48 + jj) * 66 + b]
                     + St[8448 + (48 + jj) * 66 + b] + St[12672 + (48 + jj) * 66 + b];
            if (a.addC) {
                const float* ac = a.addC + (size_t)b * 4096 + jg;
                gi += ac[0]; gf += ac[1024]; gg += ac[2048]; go += ac[3072];
            }
            if (a.bias1) {
                gi += a.bias1[jg] + a.bias2[jg];
                gf += a.bias1[1024 + jg] + a.bias2[1024 + jg];
                gg += a.bias1[2048 + jg] + a.bias2[2048 + jg];
                go += a.bias1[3072 + jg] + a.bias2[3072 + jg];
            }
            float cc2 = sigm_(gf) * a.cSt[b * HH + jg] + sigm_(gi) * tanhf(gg);
            a.cSt[b * HH + jg] = cc2;
            float h = sigm_(go) * tanhf(cc2);
            a.hF[b * HH + jg] = h;
            a.hB[(jg >> 4) * 1536 + b * 24 + (jg & 15)] = __float2half_rn(h);
        }
    } else {             // plain store (optional bias / tanh)
#pragma unroll
        for (int it = 0; it < 8; ++it) {
            int idx = tx + it * 512;
            int row = idx >> 6, col = idx & 63;
            float v = St[col * 66 + row]        + St[4224 + col * 66 + row]
                    + St[8448 + col * 66 + row] + St[12672 + col * 66 + row];
            int cg = nblk * 64 + col;
            if (a.bias1) v += a.bias1[cg] + a.bias2[cg];
            if (a.doTanh) v = tanhf(v);
            a.outC[(size_t)row * a.ldC + cg] = v;
        }
    }
}

// ------------------ X0 TMA GEMM: C[64m, 128n], K=1024 -------------------
__global__ __launch_bounds__(512, 1) void xt_k(
    const float* __restrict__ b_ih, const float* __restrict__ b_hh,
    float* __restrict__ X0) {
    extern __shared__ __align__(16) char sm[];
    const int nblk = blockIdx.x, mblk = blockIdx.y;
    const int tx = threadIdx.x;
    const int wg = tx >> 7;
    const int wtx = tx & 127;
    const int warp = wtx >> 5, lane = tx & 31;
    const int wm = warp << 4;
    const uint32_t smb = s2u(sm);
    const uint32_t wgB = smb + wg * 36864;       // 4 stages x 9216
    const uint32_t mbB = smb + 147456 + wg * 32; // 4 mbars

    const int cbase = wg * 16;                   // 16 chunks per wg

    if (wtx == 0)
        for (int s = 0; s < 4; ++s) mbar_init(mbB + s * 8, 1);
    __syncthreads();

#define XPROD(cl)                                                              \
    {                                                                          \
        int gc = cbase + (cl);                                                 \
        int s = (cl) & 3;                                                      \
        uint32_t mb = mbB + s * 8;                                             \
        uint32_t dst = wgB + s * 9216;                                         \
        expect_tx(mb, 9216);                                                   \
        bulkcp(dst, g_XEB + (size_t)mblk * 98304 + (size_t)gc * 1536, 3072, mb);\
        bulkcp(dst + 3072, g_WXB + ((size_t)nblk * 64 + gc) * 3072, 6144, mb); \
    }

    if (wtx == 0)
        for (int cl = 0; cl < 4; ++cl) XPROD(cl)

    float acc[16][4] = {};
    const uint32_t aoff = (uint32_t)((wm + (lane & 15)) * 48 + ((lane >> 4) << 4));
    const uint32_t boff = (uint32_t)(3072 + ((((lane >> 4) << 3) + (lane & 7))) * 48
                                     + (((lane >> 3) & 1) << 4));

    for (int c = 0; c < 16; ++c) {
        int s = c & 3;
        mbar_wait(mbB + s * 8, (c >> 2) & 1);
        const uint32_t base = wgB + s * 9216;
        uint32_t ah[4], bw[32];
        ldsm4(ah, base + aoff);
#pragma unroll
        for (int j = 0; j < 8; ++j)
            ldsm4(bw + 4 * j, base + boff + j * 16 * 48);
#pragma unroll
        for (int nt = 0; nt < 16; ++nt)
            mma16816(acc[nt], ah, bw + 2 * nt);
        barw(wg);
        if (wtx == 0 && c + 4 < 16) XPROD(c + 4)
    }
#undef XPROD
    __syncthreads();

    float* St = (float*)sm;
    float* Sw = St + wg * 8448;
    const int rr = wm + (lane >> 2);
#pragma unroll
    for (int nt = 0; nt < 16; ++nt) {
        int cc = nt * 8 + ((lane & 3) << 1);
        Sw[cc * 66 + rr]           = acc[nt][0];
        Sw[(cc + 1) * 66 + rr]     = acc[nt][1];
        Sw[cc * 66 + rr + 8]       = acc[nt][2];
        Sw[(cc + 1) * 66 + rr + 8] = acc[nt][3];
    }
    __syncthreads();

#pragma unroll
    for (int it = 0; it < 16; ++it) {
        int idx = tx + it * 512;
        int row = idx >> 7, col = idx & 127;
        float v = St[col * 66 + row]         + St[8448 + col * 66 + row]
                + St[16896 + col * 66 + row] + St[25344 + col * 66 + row];
        int cg = nblk * 128 + col;
        v += b_ih[cg] + b_hh[cg];
        X0[(size_t)(mblk * 64 + row) * 4096 + cg] = v;
    }
}

// ------------------------------ step kernel ----------------------------
struct StepP {
    int nL1, nOut, nL0, nQ, nAt;
    Seg l1, o, l0, q;
    const float *atQ, *atCtx;
    h16 *atWc;
    float* atP;
};

__global__ __launch_bounds__(512, 1) void step_k(StepP p) {
    extern __shared__ __align__(16) char sm[];
    const int bid = blockIdx.x;
    const int r0 = p.nAt, r1 = r0 + p.nOut, r2 = r1 + p.nL1, r3 = r2 + p.nL0;

    if (bid >= r0 && bid < r1) {
        mgemm<true, 1>(p.o, sm, bid - r0);
    } else if (bid >= r1 && bid < r2) {
        mgemm<true, 0>(p.l1, sm, bid - r1);
    } else if (bid >= r2 && bid < r3) {
        mgemm<false, 0>(p.l0, sm, bid - r2);
    } else if (bid >= r3) {
        mgemm<false, 1>(p.q, sm, bid - r3);
    } else {                              // ATTN: one block per batch b
        int b = bid;
        float* qs = (float*)sm;           // 1024 floats
        float* sc = qs + 1024;            // 64 floats
        const int tx = threadIdx.x;
        *(float2*)&qs[tx * 2] = *(const float2*)&p.atQ[(size_t)b * HH + tx * 2];
        __syncthreads();
        const int wid = tx >> 5, lane = tx & 31;
        for (int s = wid; s < SS; s += 16) {
            const float* cp = p.atCtx + ((size_t)s * BB + b) * HH;
            float acc = 0.f;
#pragma unroll
            for (int i = 0; i < 8; ++i) {
                float4 c4 = *(const float4*)(cp + i * 128 + lane * 4);
                float4 q4 = *(const float4*)&qs[i * 128 + lane * 4];
                acc += c4.x * q4.x + c4.y * q4.y + c4.z * q4.z + c4.w * q4.w;
            }
#pragma unroll
            for (int o = 16; o; o >>= 1) acc += __shfl_down_sync(0xFFFFFFFFu, acc, o);
            if (lane == 0) sc[s] = acc;
        }
        __syncthreads();
        if (tx == 0) {
            float mx = sc[0];
            for (int s = 1; s < SS; ++s) mx = fmaxf(mx, sc[s]);
            float sum = 0.f;
            for (int s = 0; s < SS; ++s) { float e = expf(sc[s] - mx); sc[s] = e; sum += e; }
            float inv = 1.f / sum;
            for (int s = 0; s < SS; ++s) sc[s] *= inv;
        }
        __syncthreads();
        if (tx < SS) p.atP[b * SS + tx] = sc[tx];
        for (int k = tx; k < HH; k += 512) {
            float acc = 0.f;
#pragma unroll 8
            for (int s = 0; s < SS; ++s)
                acc += sc[s] * p.atCtx[((size_t)s * BB + b) * HH + k];
            p.atWc[(k >> 4) * 1536 + b * 24 + (k & 15)] = __float2half_rn(acc);
        }
    }
}

// ----------------------------- init kernels ----------------------------
__global__ void pack_w(const float* __restrict__ w_ih, const float* __restrict__ w_hh,
                       const float* __restrict__ w_in, const float* __restrict__ w_out) {
    const size_t N1 = 8388608, N0 = 4194304, NQ = 1048576, NO = 2097152, NX = 4194304;
    const size_t N = N1 + N0 + NQ + NO + NX;
    for (size_t i = (size_t)blockIdx.x * 256 + threadIdx.x; i < N;
         i += (size_t)gridDim.x * 256) {
        if (i < N1) {                        // WL1: [64][128 ch] Wih1|Whh1
            size_t j = i;
            int nblk = j >> 17; j &= 131071;
            int c = j >> 10; j &= 1023;
            int row = j >> 4, kk = j & 15;
            int wr = (row >> 4) * 1024 + nblk * 16 + (row & 15);
            float v = (c < 64) ? w_ih[4194304 + (size_t)wr * 1024 + c * 16 + kk]
                               : w_hh[4194304 + (size_t)wr * 1024 + (c - 64) * 16 + kk];
            g_WL1B[((size_t)nblk * 128 + c) * 1536 + row * 24 + kk] = __float2half_rn(v);
        } else if (i < N1 + N0) {            // WL0: [64][64 ch] Whh0
            size_t j = i - N1;
            int nblk = j >> 16; j &= 65535;
            int c = j >> 10; j &= 1023;
            int row = j >> 4, kk = j & 15;
            int wr = (row >> 4) * 1024 + nblk * 16 + (row & 15);
            float v = w_hh[(size_t)wr * 1024 + c * 16 + kk];
            g_WL0B[((size_t)nblk * 64 + c) * 1536 + row * 24 + kk] = __float2half_rn(v);
        } else if (i < N1 + N0 + NQ) {       // WQ: [16][64 ch] Win
            size_t j = i - N1 - N0;
            int nblk = j >> 16; j &= 65535;
            int c = j >> 10; j &= 1023;
            int row = j >> 4, kk = j & 15;
            int wr = nblk * 64 + row;
            float v = w_in[(size_t)wr * 1024 + c * 16 + kk];
            g_WQB[((size_t)nblk * 64 + c) * 1536 + row * 24 + kk] = __float2half_rn(v);
        } else if (i < N1 + N0 + NQ + NO) {  // WO: [16][128 ch] Wo cols split
            size_t j = i - N1 - N0 - NQ;
            int nblk = j >> 17; j &= 131071;
            int c = j >> 10; j &= 1023;
            int row = j >> 4, kk = j & 15;
            int wr = nblk * 64 + row;
            float v = (c < 64) ? w_out[(size_t)wr * 2048 + c * 16 + kk]
                               : w_out[(size_t)wr * 2048 + 1024 + (c - 64) * 16 + kk];
            g_WOB[((size_t)nblk * 128 + c) * 1536 + row * 24 + kk] = __float2half_rn(v);
        } else {                             // WX: [32 nblk][64 ch][128 rows] w_ih0
            size_t j = i - N1 - N0 - NQ - NO;
            int nblk = j >> 17; j &= 131071;
            int c = j >> 11; j &= 2047;
            int row = j >> 4, kk = j & 15;
            float v = w_ih[((size_t)nblk * 128 + row) * 1024 + c * 16 + kk];
            g_WXB[((size_t)nblk * 64 + c) * 3072 + row * 24 + kk] = __float2half_rn(v);
        }
    }
}

__global__ void gather_xe(const int* __restrict__ inp, const float* __restrict__ emb) {
    size_t i = (size_t)blockIdx.x * 256 + threadIdx.x;
    if (i < 4194304) {
        size_t tb = i >> 10, k = i & 1023;
        float v = emb[(size_t)inp[tb] * 1024 + k];
        g_XEB[(tb >> 6) * 98304 + (k >> 4) * 1536 + (tb & 63) * 24 + (k & 15)] =
            __float2half_rn(v);
    }
}

__global__ void init_sk(const float* __restrict__ h0, const float* __restrict__ c0) {
    int i = blockIdx.x * 256 + threadIdx.x;
    if (i < BH) {
        int b = i >> 10, j = i & 1023;
        int off = (j >> 4) * 1536 + b * 24 + (j & 15);
        float a = h0[i], bb = h0[BH + i];
        g_h0F[1][i] = a; g_h0B[1][off] = __float2half_rn(a);   // h0(-1): slot 1
        g_h1F[3][i] = bb; g_h1B[3][off] = __float2half_rn(bb); // h1(-1): slot 3
        g_c0F[i] = c0[i];
        g_c1F[i] = c0[BH + i];
    }
}

__global__ void final_k(float* __restrict__ hf, float* __restrict__ cf,
                        float* __restrict__ at) {
    int i = blockIdx.x * 256 + threadIdx.x;
    if (i < BH) {
        hf[i] = g_h0F[1][i];            // h0(63): 63&1 = 1
        hf[BH + i] = g_h1F[3][i];       // h1(63): 63&3 = 3
        cf[i] = g_c0F[i];
        cf[BH + i] = g_c1F[i];
    }
    if (i < BB * SS) at[i] = g_attn[i];
}

// ------------------------------- launch --------------------------------
extern "C" void kernel_launch(void* const* d_in, const int* in_sizes, int n_in,
                              void* d_out, int out_size) {
    (void)in_sizes; (void)n_in; (void)out_size;
    const int*   inp   = (const int*)d_in[0];
    const float* h0    = (const float*)d_in[1];
    const float* c0    = (const float*)d_in[2];
    const float* ctx   = (const float*)d_in[3];
    const float* emb   = (const float*)d_in[4];
    const float* w_ih  = (const float*)d_in[5];
    const float* w_hh  = (const float*)d_in[6];
    const float* b_ih  = (const float*)d_in[7];
    const float* b_hh  = (const float*)d_in[8];
    const float* w_in  = (const float*)d_in[9];
    const float* w_out = (const float*)d_in[10];

    float* out  = (float*)d_out;
    float* outs = out;
    float* hf   = out + (size_t)TT * BH;
    float* cf   = hf + 2 * BH;
    float* at   = cf + 2 * BH;

    cudaFuncSetAttribute(step_k, cudaFuncAttributeMaxDynamicSharedMemorySize, SMB);
    cudaFuncSetAttribute(xt_k,   cudaFuncAttributeMaxDynamicSharedMemorySize, SMB);

    h16 *WL1B, *WL0B, *WQB, *WOB;
    h16 *h0B, *h1B, *wcB;
    float *h0F, *h1F, *c0F, *c1F, *qF, *X0, *AT;
    cudaGetSymbolAddress((void**)&WL1B, g_WL1B); cudaGetSymbolAddress((void**)&WL0B, g_WL0B);
    cudaGetSymbolAddress((void**)&WQB,  g_WQB);  cudaGetSymbolAddress((void**)&WOB,  g_WOB);
    cudaGetSymbolAddress((void**)&h0F, g_h0F); cudaGetSymbolAddress((void**)&h1F, g_h1F);
    cudaGetSymbolAddress((void**)&h0B, g_h0B); cudaGetSymbolAddress((void**)&h1B, g_h1B);
    cudaGetSymbolAddress((void**)&c0F, g_c0F); cudaGetSymbolAddress((void**)&c1F, g_c1F);
    cudaGetSymbolAddress((void**)&qF,  g_qF);
    cudaGetSymbolAddress((void**)&wcB, g_wcB);
    cudaGetSymbolAddress((void**)&X0,  g_X0);
    cudaGetSymbolAddress((void**)&AT,  g_attn);

    pack_w<<<16384, 256>>>(w_ih, w_hh, w_in, w_out);
    gather_xe<<<16384, 256>>>(inp, emb);
    init_sk<<<256, 256>>>(h0, c0);

    xt_k<<<dim3(32, 64), 512, SMB>>>(b_ih, b_hh, X0);

    // Pipeline: launch k carries L1(k-1), OUT(k-4), L0(k), Q(k-2), ATTN(k-3).
    for (int k = 0; k <= 67; ++k) {
        StepP p = {};
        int tL1 = k - 1, tL0 = k, tQ = k - 2, tAt = k - 3, tOut = k - 4;
        if (tL1 >= 0 && tL1 < TT) {
            p.nL1 = 64;
            Seg& s = p.l1;
            s.A1 = h0B + (size_t)(tL1 & 1) * 98304;
            s.A2 = h1B + (size_t)((tL1 - 1) & 3) * 98304;
            s.WB = WL1B; s.NC = 128;
            s.bias1 = b_ih + 4096; s.bias2 = b_hh + 4096;
            s.cSt = c1F;
            s.hF = h1F + (size_t)(tL1 & 3) * BH;
            s.hB = h1B + (size_t)(tL1 & 3) * 98304;
        }
        if (tOut >= 0 && tOut < TT) {
            p.nOut = 16;
            Seg& s = p.o;
            s.A1 = wcB + (size_t)(tOut & 1) * 98304;
            s.A2 = h1B + (size_t)(tOut & 3) * 98304;
            s.WB = WOB; s.NC = 128;
            s.outC = outs + (size_t)tOut * BH; s.ldC = HH; s.doTanh = 1;
        }
        if (tL0 >= 0 && tL0 < TT) {
            p.nL0 = 64;
            Seg& s = p.l0;
            s.A1 = h0B + (size_t)((tL0 + 1) & 1) * 98304;
            s.WB = WL0B; s.NC = 64;
            s.addC = X0 + (size_t)tL0 * 64 * 4096;
            s.cSt = c0F;
            s.hF = h0F + (size_t)(tL0 & 1) * BH;
            s.hB = h0B + (size_t)(tL0 & 1) * 98304;
        }
        if (tQ >= 0 && tQ < TT) {
            p.nQ = 16;
            Seg& s = p.q;
            s.A1 = h1B + (size_t)(tQ & 3) * 98304;
            s.WB = WQB; s.NC = 64;
            s.outC = qF + (size_t)(tQ & 1) * BH; s.ldC = HH; s.doTanh = 0;
        }
        if (tAt >= 0 && tAt < TT) {
            p.nAt = 64;
            p.atQ = qF + (size_t)(tAt & 1) * BH;
            p.atCtx = ctx;
            p.atWc = wcB + (size_t)(tAt & 1) * 98304;
            p.atP = AT;
        }
        int grid = p.nL1 + p.nOut + p.nL0 + p.nQ + p.nAt;
        if (grid > 0) step_k<<<grid, 512, SMB>>>(p);
    }

    final_k<<<512, 256>>>(hf, cf, at);
}